// round 4
// baseline (speedup 1.0000x reference)
#include <cuda_runtime.h>
#include <cuda_bf16.h>
#include <math.h>
#include <stdint.h>

#define BB 4
#define SS 128
#define DD 512
#define HH 8
#define DH 64
#define FF 2048
#define RR 8
#define BS (BB*SS)          // 512
#define UU 262144           // 512*512
#define THRESH 0.1f

typedef __nv_bfloat16 bf16;

// ======================= helpers =======================
__device__ __forceinline__ uint32_t smem_u32(const void* p){
    uint32_t a;
    asm("{ .reg .u64 t; cvta.to.shared.u64 t, %1; cvt.u32.u64 %0, t; }" : "=r"(a) : "l"(p));
    return a;
}
__device__ __forceinline__ void ldsm4(uint32_t& r0, uint32_t& r1, uint32_t& r2, uint32_t& r3,
                                      uint32_t addr){
    asm volatile("ldmatrix.sync.aligned.m8n8.x4.shared.b16 {%0,%1,%2,%3}, [%4];"
                 : "=r"(r0), "=r"(r1), "=r"(r2), "=r"(r3) : "r"(addr));
}
__device__ __forceinline__ void mma16816(float* d, const uint32_t* a, const uint32_t* b){
    asm volatile("mma.sync.aligned.m16n8k16.row.col.f32.bf16.bf16.f32 "
                 "{%0,%1,%2,%3}, {%4,%5,%6,%7}, {%8,%9}, {%0,%1,%2,%3};"
                 : "+f"(d[0]), "+f"(d[1]), "+f"(d[2]), "+f"(d[3])
                 : "r"(a[0]), "r"(a[1]), "r"(a[2]), "r"(a[3]), "r"(b[0]), "r"(b[1]));
}
__device__ __forceinline__ void cpa16(uint32_t s, const void* g){
    asm volatile("cp.async.cg.shared.global [%0], [%1], 16;" :: "r"(s), "l"(g));
}
__device__ __forceinline__ void cpa_commit(){
    asm volatile("cp.async.commit_group;" ::: "memory");
}
template<int N> __device__ __forceinline__ void cpa_wait(){
    asm volatile("cp.async.wait_group %0;" :: "n"(N) : "memory");
}

// ======================= scratch (device globals) =======================
__device__ bf16  g_wTh[23*UU];          // packed transposed weights, hi
__device__ bf16  g_wTl[23*UU];          // packed transposed weights, lo
__device__ float g_b3[3*DD];            // packed q/k/v biases
__device__ bf16  g_xnh[UU], g_xnl[UU];
__device__ float g_qkv[3*UU];
__device__ float g_attn[BB*HH*SS*SS];
__device__ float g_am[BB*SS*SS];
__device__ bf16  g_ctxh[UU], g_ctxl[UU];
__device__ bf16  g_aoh[UU],  g_aol[UU];
__device__ bf16  g_hidh[BS*FF], g_hidl[BS*FF];
__device__ float g_nupart[4*UU];        // split-K partials for nu
__device__ float g_nu[UU];
__device__ bf16  g_nuh[UU], g_nul[UU];
__device__ float g_ab[2*UU];
__device__ float g_trans[BS*RR*DD];     // [n][r][d]
__device__ int   g_rel[BB*SS*SS];
__device__ bf16  g_rsh[UU], g_rsl[UU];
__device__ float g_nr[UU];

struct WUnit { const float* src; int ld; long dst; int dld; };
__device__ WUnit g_wu[23];

// ======================= setup: weight-unit table + packed biases =======================
__global__ void setup_k(const float* wq, const float* wk, const float* wv, const float* wo,
                        const float* w1, const float* w2, const float* rc, const float* kg,
                        const float* s2n, const float* bq, const float* bk, const float* bvv)
{
    int t = threadIdx.x;
    if (t < DD) { g_b3[t] = bq[t]; g_b3[DD+t] = bk[t]; g_b3[2*DD+t] = bvv[t]; }
    if (t == 0) {
        const float* qkv[3] = {wq, wk, wv};
        for (int u = 0; u < 3; u++) g_wu[u] = {qkv[u], DD, (long)u*UU, DD};
        g_wu[3] = {wo, DD, 3L*UU, DD};
        for (int u = 0; u < 4; u++)                       // w1 [512][2048] -> [2048][512]
            g_wu[4+u] = {w1 + u*DD, FF, 4L*UU + (long)u*UU, DD};
        for (int u = 0; u < 4; u++)                       // w2 [2048][512] -> [512][2048]
            g_wu[8+u] = {w2 + (long)u*UU, DD, 8L*UU + (long)u*DD, FF};
        for (int u = 0; u < 2; u++)
            g_wu[12+u] = {rc + (long)u*UU, DD, (12L+u)*UU, DD};
        for (int u = 0; u < 8; u++)
            g_wu[14+u] = {kg + (long)u*UU, DD, (14L+u)*UU, DD};
        g_wu[22] = {s2n, DD, 22L*UU, DD};
    }
}

// ======================= weight transpose + fp32 -> bf16 hi/lo =======================
__global__ void wconv_k()
{
    __shared__ float tile[32][33];
    WUnit u = g_wu[blockIdx.z];
    int k0 = blockIdx.y * 32, n0 = blockIdx.x * 32;
    int tx = threadIdx.x, ty = threadIdx.y;        // (32, 8)
#pragma unroll
    for (int i = 0; i < 4; i++)
        tile[ty + 8*i][tx] = __ldg(u.src + (long)(k0 + ty + 8*i) * u.ld + n0 + tx);
    __syncthreads();
#pragma unroll
    for (int i = 0; i < 4; i++) {
        int n = n0 + ty + 8*i, k = k0 + tx;
        float v = tile[tx][ty + 8*i];
        bf16 h = __float2bfloat16(v);
        bf16 l = __float2bfloat16(v - __bfloat162float(h));
        long off = u.dst + (long)n * u.dld + k;
        g_wTh[off] = h; g_wTl[off] = l;
    }
}

// ======================= mma.sync bf16 3-pass GEMM, cp.async 2-stage =======================
// C[M,N] = A @ B^T. A hi/lo: [M][K] row-major (+ z*a_z). B hi/lo: [N][K] row-major (+ z*b_z).
// CTA tile 64x64, 8 warps (warp tile 32x16), K-chunk 64, double-buffered.
#define FL_F32  1
#define FL_HILO 2
#define FL_RELU 4

#define TSTRIDE 144                      // smem row stride bytes (72 bf16)
#define TILE_B  9216                     // 64 rows * 144 B
#define STAGE_B 36864                    // 4 tiles
#define GSM     73728                    // 2 stages

__global__ void __launch_bounds__(256)
gemm_mma(const bf16* __restrict__ Ah, const bf16* __restrict__ Al, int lda, long a_z,
         const bf16* __restrict__ Bh, const bf16* __restrict__ Bl, long b_z, int ldb,
         const float* __restrict__ bias, int bias_z,
         float* __restrict__ C, long c_z, int ldc,
         bf16* __restrict__ Ch, bf16* __restrict__ Cl, int ldch,
         int K, int flags)
{
    extern __shared__ char sm[];
    uint32_t sb = smem_u32(sm);
    const int tid = threadIdx.x, lane = tid & 31, wid = tid >> 5;
    const int wm = wid >> 2, wn = wid & 3;               // warp grid 2 x 4
    const int m0 = blockIdx.y * 64, n0 = blockIdx.x * 64, z = blockIdx.z;
    const bf16* Ahp = Ah + (long)z * a_z;
    const bf16* Alp = Al + (long)z * a_z;
    const bf16* Bhp = Bh + (long)z * b_z;
    const bf16* Blp = Bl + (long)z * b_z;

    // cp.async mapping: idx = tid + seg*256 -> row idx>>3, 16B-seg idx&7
    const int ld_r = tid >> 3, ld_c = (tid & 7) * 8;     // row, col(elements) for seg 0
    // seg1: row += 32
    const uint32_t s_wr = (uint32_t)(ld_r * TSTRIDE + ld_c * 2);

    // ldmatrix lane addressing
    const int a_r = (lane & 7) + ((lane >> 3) & 1) * 8;
    const int a_c8 = (lane >> 4) * 8;
    const uint32_t aoff = (uint32_t)((wm * 32 + a_r) * TSTRIDE + a_c8 * 2);
    const int b_r = (lane & 7) + (lane >> 4) * 8;
    const int b_c8 = ((lane >> 3) & 1) * 8;
    const uint32_t boff = (uint32_t)((wn * 16 + b_r) * TSTRIDE + b_c8 * 2);

    float acc[2][2][4];
#pragma unroll
    for (int i = 0; i < 2; i++)
#pragma unroll
        for (int j = 0; j < 2; j++)
#pragma unroll
            for (int q = 0; q < 4; q++) acc[i][j][q] = 0.f;

    const int nch = K >> 6;

    auto issue = [&](int kk, int st){
        uint32_t base = sb + st * STAGE_B + s_wr;
        const bf16* ga0 = Ahp + (long)(m0 + ld_r) * lda + kk + ld_c;
        const bf16* ga1 = Alp + (long)(m0 + ld_r) * lda + kk + ld_c;
        const bf16* gb0 = Bhp + (long)(n0 + ld_r) * ldb + kk + ld_c;
        const bf16* gb1 = Blp + (long)(n0 + ld_r) * ldb + kk + ld_c;
        cpa16(base,                         ga0);
        cpa16(base + 32 * TSTRIDE,          ga0 + 32 * lda);
        cpa16(base + TILE_B,                ga1);
        cpa16(base + TILE_B + 32 * TSTRIDE, ga1 + 32 * lda);
        cpa16(base + 2 * TILE_B,                gb0);
        cpa16(base + 2 * TILE_B + 32 * TSTRIDE, gb0 + 32 * ldb);
        cpa16(base + 3 * TILE_B,                gb1);
        cpa16(base + 3 * TILE_B + 32 * TSTRIDE, gb1 + 32 * ldb);
        cpa_commit();
    };

    issue(0, 0);
    for (int i = 0; i < nch; i++) {
        if (i + 1 < nch) { issue((i + 1) << 6, (i + 1) & 1); cpa_wait<1>(); }
        else             { cpa_wait<0>(); }
        __syncthreads();

        uint32_t st = sb + (i & 1) * STAGE_B;
#pragma unroll
        for (int ks = 0; ks < 4; ks++) {
            uint32_t kb = ks * 32;
            uint32_t ah[2][4], al[2][4], bh[2][2], bl[2][2];
            ldsm4(bh[0][0], bh[0][1], bh[1][0], bh[1][1], st + 2*TILE_B + boff + kb);
            ldsm4(bl[0][0], bl[0][1], bl[1][0], bl[1][1], st + 3*TILE_B + boff + kb);
#pragma unroll
            for (int mf = 0; mf < 2; mf++)
                ldsm4(ah[mf][0], ah[mf][1], ah[mf][2], ah[mf][3],
                      st + aoff + mf * (16*TSTRIDE) + kb);
#pragma unroll
            for (int mf = 0; mf < 2; mf++)
                ldsm4(al[mf][0], al[mf][1], al[mf][2], al[mf][3],
                      st + TILE_B + aoff + mf * (16*TSTRIDE) + kb);
#pragma unroll
            for (int mf = 0; mf < 2; mf++)
#pragma unroll
                for (int nf = 0; nf < 2; nf++) mma16816(acc[mf][nf], ah[mf], bh[nf]);
#pragma unroll
            for (int mf = 0; mf < 2; mf++)
#pragma unroll
                for (int nf = 0; nf < 2; nf++) mma16816(acc[mf][nf], ah[mf], bl[nf]);
#pragma unroll
            for (int mf = 0; mf < 2; mf++)
#pragma unroll
                for (int nf = 0; nf < 2; nf++) mma16816(acc[mf][nf], al[mf], bh[nf]);
        }
        __syncthreads();
    }

    // epilogue (registers -> gmem)
    const int g = lane >> 2, tg = lane & 3;
    const float* bp = bias ? bias + (long)z * bias_z : nullptr;
    float* Cz = C ? C + (long)z * c_z : nullptr;
#pragma unroll
    for (int mf = 0; mf < 2; mf++) {
#pragma unroll
        for (int nf = 0; nf < 2; nf++) {
            int row = m0 + wm * 32 + mf * 16 + g;
            int col = n0 + wn * 16 + nf * 8 + tg * 2;
            float v0 = acc[mf][nf][0], v1 = acc[mf][nf][1];
            float v2 = acc[mf][nf][2], v3 = acc[mf][nf][3];
            if (bp) {
                float bb0 = __ldg(bp + col), bb1 = __ldg(bp + col + 1);
                v0 += bb0; v1 += bb1; v2 += bb0; v3 += bb1;
            }
            if (flags & FL_RELU) {
                v0 = fmaxf(v0, 0.f); v1 = fmaxf(v1, 0.f);
                v2 = fmaxf(v2, 0.f); v3 = fmaxf(v3, 0.f);
            }
            if (flags & FL_F32) {
                *(float2*)&Cz[(long)row * ldc + col] = make_float2(v0, v1);
                *(float2*)&Cz[(long)(row + 8) * ldc + col] = make_float2(v2, v3);
            }
            if (flags & FL_HILO) {
                bf16 h0 = __float2bfloat16(v0), h1 = __float2bfloat16(v1);
                bf16 h2 = __float2bfloat16(v2), h3 = __float2bfloat16(v3);
                __nv_bfloat162 ph0; ph0.x = h0; ph0.y = h1;
                __nv_bfloat162 ph1; ph1.x = h2; ph1.y = h3;
                __nv_bfloat162 pl0, pl1;
                pl0.x = __float2bfloat16(v0 - __bfloat162float(h0));
                pl0.y = __float2bfloat16(v1 - __bfloat162float(h1));
                pl1.x = __float2bfloat16(v2 - __bfloat162float(h2));
                pl1.y = __float2bfloat16(v3 - __bfloat162float(h3));
                *(__nv_bfloat162*)&Ch[(long)row * ldch + col] = ph0;
                *(__nv_bfloat162*)&Cl[(long)row * ldch + col] = pl0;
                *(__nv_bfloat162*)&Ch[(long)(row + 8) * ldch + col] = ph1;
                *(__nv_bfloat162*)&Cl[(long)(row + 8) * ldch + col] = pl1;
            }
        }
    }
}

// ======================= LayerNorm 1 (writes bf16 hi/lo) =======================
__global__ void ln1_k(const float* __restrict__ in, const float* __restrict__ g,
                      const float* __restrict__ b, bf16* __restrict__ oh, bf16* __restrict__ ol)
{
    int row = blockIdx.x, t = threadIdx.x;   // 256 threads
    __shared__ float rbuf[256];
    long base = (long)row * DD;
    float v0 = in[base + t], v1 = in[base + t + 256];
    rbuf[t] = v0 + v1; __syncthreads();
    for (int s = 128; s > 0; s >>= 1) { if (t < s) rbuf[t] += rbuf[t + s]; __syncthreads(); }
    float mean = rbuf[0] * (1.0f / 512.0f);
    __syncthreads();
    float d0 = v0 - mean, d1 = v1 - mean;
    rbuf[t] = d0 * d0 + d1 * d1; __syncthreads();
    for (int s = 128; s > 0; s >>= 1) { if (t < s) rbuf[t] += rbuf[t + s]; __syncthreads(); }
    float rs = rsqrtf(rbuf[0] * (1.0f / 512.0f) + 1e-5f);
    float o0 = d0 * rs * g[t] + b[t];
    float o1 = d1 * rs * g[t + 256] + b[t + 256];
    bf16 h0 = __float2bfloat16(o0), h1 = __float2bfloat16(o1);
    oh[base + t] = h0;       ol[base + t]       = __float2bfloat16(o0 - __bfloat162float(h0));
    oh[base + t + 256] = h1; ol[base + t + 256] = __float2bfloat16(o1 - __bfloat162float(h1));
}

// ======================= LayerNorm 2 (residual, fp32 out) =======================
__global__ void ln2_k(const float* __restrict__ in, const float* __restrict__ add,
                      const float* __restrict__ g, const float* __restrict__ b,
                      float* __restrict__ out)
{
    int row = blockIdx.x, t = threadIdx.x;
    __shared__ float rbuf[256];
    long base = (long)row * DD;
    float v0 = in[base + t] + add[base + t];
    float v1 = in[base + t + 256] + add[base + t + 256];
    rbuf[t] = v0 + v1; __syncthreads();
    for (int s = 128; s > 0; s >>= 1) { if (t < s) rbuf[t] += rbuf[t + s]; __syncthreads(); }
    float mean = rbuf[0] * (1.0f / 512.0f);
    __syncthreads();
    float d0 = v0 - mean, d1 = v1 - mean;
    rbuf[t] = d0 * d0 + d1 * d1; __syncthreads();
    for (int s = 128; s > 0; s >>= 1) { if (t < s) rbuf[t] += rbuf[t + s]; __syncthreads(); }
    float rs = rsqrtf(rbuf[0] * (1.0f / 512.0f) + 1e-5f);
    out[base + t]       = d0 * rs * g[t]       + b[t];
    out[base + t + 256] = d1 * rs * g[t + 256] + b[t + 256];
}

// ======================= attention =======================
__global__ void attn_scores_k(const float* __restrict__ q, const float* __restrict__ k,
                              float* __restrict__ attn)
{
    int i = blockIdx.x, h = blockIdx.y, b = blockIdx.z, t = threadIdx.x; // 128 thr
    __shared__ float ks[SS][DH + 1];
    __shared__ float qs[DH];
    __shared__ float red[SS];
    const float* kbase = k + (long)b * SS * DD + h * DH;
    for (int idx = t; idx < SS * DH; idx += 128) {
        int j = idx >> 6, d = idx & 63;
        ks[j][d] = kbase[(long)j * DD + d];
    }
    if (t < DH) qs[t] = q[(long)(b * SS + i) * DD + h * DH + t];
    __syncthreads();
    float acc = 0.f;
#pragma unroll
    for (int d = 0; d < DH; d++) acc += qs[d] * ks[t][d];
    acc *= 0.125f;
    red[t] = acc; __syncthreads();
    for (int s = 64; s > 0; s >>= 1) { if (t < s) red[t] = fmaxf(red[t], red[t + s]); __syncthreads(); }
    float mx = red[0]; __syncthreads();
    float e = expf(acc - mx);
    red[t] = e; __syncthreads();
    for (int s = 64; s > 0; s >>= 1) { if (t < s) red[t] += red[t + s]; __syncthreads(); }
    attn[(((long)(b * HH + h) * SS) + i) * SS + t] = e / red[0];
}

__global__ void am_k(const float* __restrict__ attn, float* __restrict__ am)
{
    int bi = blockIdx.x;
    int b = bi >> 7, i = bi & 127, t = threadIdx.x;  // 128 thr
    float s = 0.f;
#pragma unroll
    for (int h = 0; h < HH; h++)
        s += attn[(((long)(b * HH + h) * SS) + i) * SS + t];
    am[(long)bi * SS + t] = s * 0.125f;
}

__global__ void attn_ctx_k(const float* __restrict__ attn, const float* __restrict__ v,
                           bf16* __restrict__ ch, bf16* __restrict__ cl)
{
    int i = blockIdx.x, h = blockIdx.y, b = blockIdx.z, t = threadIdx.x; // 64 thr
    __shared__ float at[SS];
    long arow = (((long)(b * HH + h) * SS) + i) * SS;
    at[t] = attn[arow + t]; at[t + 64] = attn[arow + t + 64];
    __syncthreads();
    float acc = 0.f;
    const float* vb = v + (long)b * SS * DD + h * DH + t;
#pragma unroll 8
    for (int j = 0; j < SS; j++) acc += at[j] * vb[(long)j * DD];
    long o = (long)(b * SS + i) * DD + h * DH + t;
    bf16 hh = __float2bfloat16(acc);
    ch[o] = hh; cl[o] = __float2bfloat16(acc - __bfloat162float(hh));
}

// ======================= nu: reduce split-K partials + bias + hi/lo =======================
__global__ void conv_nu_k(const float* __restrict__ P, const float* __restrict__ b2,
                          float* __restrict__ nu, bf16* __restrict__ H, bf16* __restrict__ L)
{
    int row = blockIdx.x, t = threadIdx.x;  // 256
    for (int c = t; c < DD; c += 256) {
        long i = (long)row * DD + c;
        float v = b2[c] + P[i] + P[UU + i] + P[2L*UU + i] + P[3L*UU + i];
        nu[i] = v;
        bf16 h = __float2bfloat16(v);
        H[i] = h; L[i] = __float2bfloat16(v - __bfloat162float(h));
    }
}

// ======================= pair relation classifier =======================
__global__ void pair_k(const float* __restrict__ ap, const float* __restrict__ bp,
                       const float* __restrict__ rc_b1, const float* __restrict__ rc_w2,
                       const float* __restrict__ rc_b2, const float* __restrict__ am,
                       int* __restrict__ rel)
{
    int b = blockIdx.z;
    int u0 = blockIdx.y * 16, v0 = blockIdx.x * 16;
    int t = threadIdx.x;                 // 256
    int ul = t >> 4, vl = t & 15;
    __shared__ float sA[16][65], sB[16][65], sW[64][8], sC[64];
    float acc[RR];
#pragma unroll
    for (int r = 0; r < RR; r++) acc[r] = rc_b2[r];

    for (int c0 = 0; c0 < DD; c0 += 64) {
        for (int idx = t; idx < 1024; idx += 256) {
            int rr = idx >> 6, cc = idx & 63;
            sA[rr][cc] = ap[(long)(b * SS + u0 + rr) * DD + c0 + cc];
            sB[rr][cc] = bp[(long)(b * SS + v0 + rr) * DD + c0 + cc];
        }
        for (int idx = t; idx < 512; idx += 256)
            sW[idx >> 3][idx & 7] = rc_w2[(long)(c0 + (idx >> 3)) * RR + (idx & 7)];
        if (t < 64) sC[t] = rc_b1[c0 + t];
        __syncthreads();
#pragma unroll 4
        for (int dd = 0; dd < 64; dd++) {
            float hsum = sA[ul][dd] + sB[vl][dd] + sC[dd];
            hsum = fmaxf(hsum, 0.f);
            float4 w0 = *(float4*)&sW[dd][0];
            float4 w1 = *(float4*)&sW[dd][4];
            acc[0] += hsum * w0.x; acc[1] += hsum * w0.y;
            acc[2] += hsum * w0.z; acc[3] += hsum * w0.w;
            acc[4] += hsum * w1.x; acc[5] += hsum * w1.y;
            acc[6] += hsum * w1.z; acc[7] += hsum * w1.w;
        }
        __syncthreads();
    }
    int pred = 0; float best = acc[0];
#pragma unroll
    for (int r = 1; r < RR; r++) if (acc[r] > best) { best = acc[r]; pred = r; }
    int u = u0 + ul, v = v0 + vl;
    float amv = am[((long)b * SS + u) * SS + v];
    int valid = (amv > THRESH) && (u != v) && (pred != 0);
    rel[((long)b * SS + u) * SS + v] = valid ? pred : 0;
}

// ======================= edge aggregation (writes reasoned hi/lo) =======================
__global__ void agg_k(const int* __restrict__ rel, const float* __restrict__ trans,
                      const float* __restrict__ nu, bf16* __restrict__ rh, bf16* __restrict__ rl)
{
    int bv = blockIdx.x;                 // b*S + v
    int b = bv >> 7, v = bv & 127, t = threadIdx.x;   // 256
    __shared__ int sr[SS];
    if (t < SS) sr[t] = rel[((long)b * SS + t) * SS + v];
    __syncthreads();
    float a0 = 0.f, a1 = 0.f;
    for (int u = 0; u < SS; u++) {
        int r = sr[u];
        if (r) {
            const float* tr = trans + ((long)(b * SS + u) * RR + r) * DD;
            a0 += tr[t]; a1 += tr[t + 256];
        }
    }
    long row = (long)bv * DD;
    float v0 = nu[row + t] + a0;
    float v1 = nu[row + t + 256] + a1;
    bf16 h0 = __float2bfloat16(v0), h1 = __float2bfloat16(v1);
    rh[row + t] = h0;       rl[row + t]       = __float2bfloat16(v0 - __bfloat162float(h0));
    rh[row + t + 256] = h1; rl[row + t + 256] = __float2bfloat16(v1 - __bfloat162float(h1));
}

// ======================= launch =======================
extern "C" void kernel_launch(void* const* d_in, const int* in_sizes, int n_in,
                              void* d_out, int out_size)
{
    const float* x     = (const float*)d_in[0];
    const float* ln1_g = (const float*)d_in[1];
    const float* ln1_b = (const float*)d_in[2];
    const float* wq    = (const float*)d_in[3];
    const float* bq    = (const float*)d_in[4];
    const float* wk    = (const float*)d_in[5];
    const float* bk    = (const float*)d_in[6];
    const float* wv    = (const float*)d_in[7];
    const float* bvv   = (const float*)d_in[8];
    const float* wo    = (const float*)d_in[9];
    const float* bo    = (const float*)d_in[10];
    const float* w1    = (const float*)d_in[11];
    const float* b1    = (const float*)d_in[12];
    const float* w2    = (const float*)d_in[13];
    const float* b2    = (const float*)d_in[14];
    const float* rc_w1 = (const float*)d_in[15];
    const float* rc_b1 = (const float*)d_in[16];
    const float* rc_w2 = (const float*)d_in[17];
    const float* rc_b2 = (const float*)d_in[18];
    const float* kg_w  = (const float*)d_in[19];
    const float* s2n_w = (const float*)d_in[20];
    const float* s2n_b = (const float*)d_in[21];
    const float* ln2_g = (const float*)d_in[22];
    const float* ln2_b = (const float*)d_in[23];
    float* out = (float*)d_out;

    bf16 *wTh, *wTl, *xnh, *xnl, *ctxh, *ctxl, *aoh, *aol, *hidh, *hidl, *nuh, *nul, *rsh, *rsl;
    float *b3, *qkv, *attn, *am, *nupart, *nu, *ab, *trans, *nr;
    int *rel;
    cudaGetSymbolAddress((void**)&wTh, g_wTh);   cudaGetSymbolAddress((void**)&wTl, g_wTl);
    cudaGetSymbolAddress((void**)&b3, g_b3);
    cudaGetSymbolAddress((void**)&xnh, g_xnh);   cudaGetSymbolAddress((void**)&xnl, g_xnl);
    cudaGetSymbolAddress((void**)&qkv, g_qkv);
    cudaGetSymbolAddress((void**)&attn, g_attn); cudaGetSymbolAddress((void**)&am, g_am);
    cudaGetSymbolAddress((void**)&ctxh, g_ctxh); cudaGetSymbolAddress((void**)&ctxl, g_ctxl);
    cudaGetSymbolAddress((void**)&aoh, g_aoh);   cudaGetSymbolAddress((void**)&aol, g_aol);
    cudaGetSymbolAddress((void**)&hidh, g_hidh); cudaGetSymbolAddress((void**)&hidl, g_hidl);
    cudaGetSymbolAddress((void**)&nupart, g_nupart);
    cudaGetSymbolAddress((void**)&nu, g_nu);
    cudaGetSymbolAddress((void**)&nuh, g_nuh);   cudaGetSymbolAddress((void**)&nul, g_nul);
    cudaGetSymbolAddress((void**)&ab, g_ab);
    cudaGetSymbolAddress((void**)&trans, g_trans);
    cudaGetSymbolAddress((void**)&rel, g_rel);
    cudaGetSymbolAddress((void**)&rsh, g_rsh);   cudaGetSymbolAddress((void**)&rsl, g_rsl);
    cudaGetSymbolAddress((void**)&nr, g_nr);

    cudaFuncSetAttribute(gemm_mma, cudaFuncAttributeMaxDynamicSharedMemorySize, GSM);

    // weight prep
    setup_k<<<1, 512>>>(wq, wk, wv, wo, w1, w2, rc_w1, kg_w, s2n_w, bq, bk, bvv);
    wconv_k<<<dim3(16, 16, 23), dim3(32, 8)>>>();

    // ln1 -> xn (hi/lo)
    ln1_k<<<BS, 256>>>(x, ln1_g, ln1_b, xnh, xnl);

    // QKV (z=3), fp32 out
    gemm_mma<<<dim3(8, 8, 3), 256, GSM>>>(xnh, xnl, DD, 0, wTh, wTl, UU, DD,
                                          b3, DD, qkv, UU, DD, nullptr, nullptr, 0,
                                          DD, FL_F32);
    // attention
    attn_scores_k<<<dim3(SS, HH, BB), 128>>>(qkv, qkv + UU, attn);
    am_k<<<BS, 128>>>(attn, am);
    attn_ctx_k<<<dim3(SS, HH, BB), 64>>>(attn, qkv + 2 * UU, ctxh, ctxl);

    // ao = ctx @ wo + bo  (hi/lo only)
    gemm_mma<<<dim3(8, 8, 1), 256, GSM>>>(ctxh, ctxl, DD, 0, wTh + 3L*UU, wTl + 3L*UU, 0, DD,
                                          bo, 0, nullptr, 0, 0, aoh, aol, DD,
                                          DD, FL_HILO);
    // hid = relu(ao @ w1 + b1) (hi/lo only, N=2048)
    gemm_mma<<<dim3(32, 8, 1), 256, GSM>>>(aoh, aol, DD, 0, wTh + 4L*UU, wTl + 4L*UU, 0, DD,
                                           b1, 0, nullptr, 0, 0, hidh, hidl, FF,
                                           DD, FL_HILO | FL_RELU);
    // nu partials = hid @ w2  (split-K z=4 into 4 slabs)
    gemm_mma<<<dim3(8, 8, 4), 256, GSM>>>(hidh, hidl, FF, DD, wTh + 8L*UU, wTl + 8L*UU, DD, FF,
                                          nullptr, 0, nupart, UU, DD, nullptr, nullptr, 0,
                                          DD, FL_F32);
    conv_nu_k<<<BS, 256>>>(nupart, b2, nu, nuh, nul);

    // a/b parts (z=2) and RGCN transforms (z=8), fp32
    gemm_mma<<<dim3(8, 8, 2), 256, GSM>>>(nuh, nul, DD, 0, wTh + 12L*UU, wTl + 12L*UU, UU, DD,
                                          nullptr, 0, ab, UU, DD, nullptr, nullptr, 0,
                                          DD, FL_F32);
    gemm_mma<<<dim3(8, 8, 8), 256, GSM>>>(nuh, nul, DD, 0, wTh + 14L*UU, wTl + 14L*UU, UU, DD,
                                          nullptr, 0, trans, DD, RR * DD, nullptr, nullptr, 0,
                                          DD, FL_F32);
    // edges + aggregation
    pair_k<<<dim3(8, 8, BB), 256>>>(ab, ab + UU, rc_b1, rc_w2, rc_b2, am, rel);
    agg_k<<<BS, 256>>>(rel, trans, nu, rsh, rsl);

    // s2n projection, fp32
    gemm_mma<<<dim3(8, 8, 1), 256, GSM>>>(rsh, rsl, DD, 0, wTh + 22L*UU, wTl + 22L*UU, 0, DD,
                                          s2n_b, 0, nr, 0, DD, nullptr, nullptr, 0,
                                          DD, FL_F32);
    // final residual LN
    ln2_k<<<BS, 256>>>(nr, x, ln2_g, ln2_b, out);
}

// round 5
// speedup vs baseline: 1.4902x; 1.4902x over previous
#include <cuda_runtime.h>
#include <cuda_bf16.h>
#include <math.h>
#include <stdint.h>

#define BB 4
#define SS 128
#define DD 512
#define HH 8
#define DH 64
#define FF 2048
#define RR 8
#define BS (BB*SS)          // 512
#define UU 262144           // 512*512
#define THRESH 0.1f

typedef __nv_bfloat16 bf16;

// ======================= helpers =======================
__device__ __forceinline__ uint32_t smem_u32(const void* p){
    uint32_t a;
    asm("{ .reg .u64 t; cvta.to.shared.u64 t, %1; cvt.u32.u64 %0, t; }" : "=r"(a) : "l"(p));
    return a;
}
__device__ __forceinline__ void ldsm4(uint32_t& r0, uint32_t& r1, uint32_t& r2, uint32_t& r3,
                                      uint32_t addr){
    asm volatile("ldmatrix.sync.aligned.m8n8.x4.shared.b16 {%0,%1,%2,%3}, [%4];"
                 : "=r"(r0), "=r"(r1), "=r"(r2), "=r"(r3) : "r"(addr));
}
__device__ __forceinline__ void mma16816(float* d, const uint32_t* a, const uint32_t* b){
    asm volatile("mma.sync.aligned.m16n8k16.row.col.f32.bf16.bf16.f32 "
                 "{%0,%1,%2,%3}, {%4,%5,%6,%7}, {%8,%9}, {%0,%1,%2,%3};"
                 : "+f"(d[0]), "+f"(d[1]), "+f"(d[2]), "+f"(d[3])
                 : "r"(a[0]), "r"(a[1]), "r"(a[2]), "r"(a[3]), "r"(b[0]), "r"(b[1]));
}
__device__ __forceinline__ void cpa16(uint32_t s, const void* g){
    asm volatile("cp.async.cg.shared.global [%0], [%1], 16;" :: "r"(s), "l"(g));
}
__device__ __forceinline__ void cpa_commit(){
    asm volatile("cp.async.commit_group;" ::: "memory");
}
template<int N> __device__ __forceinline__ void cpa_wait(){
    asm volatile("cp.async.wait_group %0;" :: "n"(N) : "memory");
}

// ======================= scratch (device globals) =======================
__device__ bf16  g_wTh[23*UU];          // packed transposed weights, hi
__device__ bf16  g_wTl[23*UU];          // packed transposed weights, lo
__device__ float g_b3[3*DD];            // packed q/k/v biases
__device__ bf16  g_xnh[UU], g_xnl[UU];
__device__ float g_qkv[3*UU];
__device__ float g_attn[BB*HH*SS*SS];
__device__ float g_am[BB*SS*SS];
__device__ bf16  g_ctxh[UU], g_ctxl[UU];
__device__ bf16  g_aoh[UU],  g_aol[UU];
__device__ bf16  g_hidh[BS*FF], g_hidl[BS*FF];
__device__ float g_nupart[4*UU];        // split-K partials for nu
__device__ float g_nu[UU];
__device__ bf16  g_nuh[UU], g_nul[UU];
__device__ float g_ab[2*UU];
__device__ float g_trans[BS*RR*DD];     // [n][r][d]
__device__ int   g_rel[BB*SS*SS];
__device__ bf16  g_rsh[UU], g_rsl[UU];
__device__ float g_nr[UU];

struct WUnit { const float* src; int ld; long dst; int dld; };
__device__ WUnit g_wu[23];

// ======================= setup: weight-unit table + packed biases =======================
__global__ void setup_k(const float* wq, const float* wk, const float* wv, const float* wo,
                        const float* w1, const float* w2, const float* rc, const float* kg,
                        const float* s2n, const float* bq, const float* bk, const float* bvv)
{
    int t = threadIdx.x;
    if (t < DD) { g_b3[t] = bq[t]; g_b3[DD+t] = bk[t]; g_b3[2*DD+t] = bvv[t]; }
    if (t == 0) {
        const float* qkv[3] = {wq, wk, wv};
        for (int u = 0; u < 3; u++) g_wu[u] = {qkv[u], DD, (long)u*UU, DD};
        g_wu[3] = {wo, DD, 3L*UU, DD};
        for (int u = 0; u < 4; u++)                       // w1 [512][2048] -> [2048][512]
            g_wu[4+u] = {w1 + u*DD, FF, 4L*UU + (long)u*UU, DD};
        for (int u = 0; u < 4; u++)                       // w2 [2048][512] -> [512][2048]
            g_wu[8+u] = {w2 + (long)u*UU, DD, 8L*UU + (long)u*DD, FF};
        for (int u = 0; u < 2; u++)
            g_wu[12+u] = {rc + (long)u*UU, DD, (12L+u)*UU, DD};
        for (int u = 0; u < 8; u++)
            g_wu[14+u] = {kg + (long)u*UU, DD, (14L+u)*UU, DD};
        g_wu[22] = {s2n, DD, 22L*UU, DD};
    }
}

// ======================= weight transpose + fp32 -> bf16 hi/lo =======================
__global__ void wconv_k()
{
    __shared__ float tile[32][33];
    WUnit u = g_wu[blockIdx.z];
    int k0 = blockIdx.y * 32, n0 = blockIdx.x * 32;
    int tx = threadIdx.x, ty = threadIdx.y;        // (32, 8)
#pragma unroll
    for (int i = 0; i < 4; i++)
        tile[ty + 8*i][tx] = __ldg(u.src + (long)(k0 + ty + 8*i) * u.ld + n0 + tx);
    __syncthreads();
#pragma unroll
    for (int i = 0; i < 4; i++) {
        int n = n0 + ty + 8*i, k = k0 + tx;
        float v = tile[tx][ty + 8*i];
        bf16 h = __float2bfloat16(v);
        bf16 l = __float2bfloat16(v - __bfloat162float(h));
        long off = u.dst + (long)n * u.dld + k;
        g_wTh[off] = h; g_wTl[off] = l;
    }
}

// ======================= mma.sync bf16 3-pass GEMM, cp.async 2-stage =======================
// C[M,N] = A @ B^T. A hi/lo: [M][K] row-major (+ z*a_z). B hi/lo: [N][K] row-major (+ z*b_z).
// CTA tile 64x64, 8 warps (warp tile 32x16), K-chunk 64, double-buffered smem +
// register double-buffered fragments (ldsm for ks+1 overlaps MMAs of ks).
#define FL_F32  1
#define FL_HILO 2
#define FL_RELU 4

#define TSTRIDE 144                      // smem row stride bytes (72 bf16)
#define TILE_B  9216                     // 64 rows * 144 B
#define STAGE_B 36864                    // 4 tiles
#define GSM     73728                    // 2 stages

__global__ void __launch_bounds__(256, 2)
gemm_mma(const bf16* __restrict__ Ah, const bf16* __restrict__ Al, int lda, long a_z,
         const bf16* __restrict__ Bh, const bf16* __restrict__ Bl, long b_z, int ldb,
         const float* __restrict__ bias, int bias_z,
         float* __restrict__ C, long c_z, int ldc,
         bf16* __restrict__ Ch, bf16* __restrict__ Cl, int ldch,
         int K, int flags)
{
    extern __shared__ char sm[];
    uint32_t sb = smem_u32(sm);
    const int tid = threadIdx.x, lane = tid & 31, wid = tid >> 5;
    const int wm = wid >> 2, wn = wid & 3;               // warp grid 2 x 4
    const int m0 = blockIdx.y * 64, n0 = blockIdx.x * 64, z = blockIdx.z;
    const bf16* Ahp = Ah + (long)z * a_z;
    const bf16* Alp = Al + (long)z * a_z;
    const bf16* Bhp = Bh + (long)z * b_z;
    const bf16* Blp = Bl + (long)z * b_z;

    // cp.async mapping: row tid>>3, 16B seg tid&7 (two row-groups of 32)
    const int ld_r = tid >> 3, ld_c = (tid & 7) * 8;
    const uint32_t s_wr = (uint32_t)(ld_r * TSTRIDE + ld_c * 2);

    // ldmatrix lane addressing
    const int a_r = (lane & 7) + ((lane >> 3) & 1) * 8;
    const int a_c8 = (lane >> 4) * 8;
    const uint32_t aoff = (uint32_t)((wm * 32 + a_r) * TSTRIDE + a_c8 * 2);
    const int b_r = (lane & 7) + (lane >> 4) * 8;
    const int b_c8 = ((lane >> 3) & 1) * 8;
    const uint32_t boff = (uint32_t)((wn * 16 + b_r) * TSTRIDE + b_c8 * 2);

    float acc[2][2][4];
#pragma unroll
    for (int i = 0; i < 2; i++)
#pragma unroll
        for (int j = 0; j < 2; j++)
#pragma unroll
            for (int q = 0; q < 4; q++) acc[i][j][q] = 0.f;

    // register fragment double buffers
    uint32_t fah[2][2][4], fal[2][2][4], fbh[2][2][2], fbl[2][2][2];

    const int nch = K >> 6;

    auto issue = [&](int kk, int st){
        uint32_t base = sb + st * STAGE_B + s_wr;
        const bf16* ga0 = Ahp + (long)(m0 + ld_r) * lda + kk + ld_c;
        const bf16* ga1 = Alp + (long)(m0 + ld_r) * lda + kk + ld_c;
        const bf16* gb0 = Bhp + (long)(n0 + ld_r) * ldb + kk + ld_c;
        const bf16* gb1 = Blp + (long)(n0 + ld_r) * ldb + kk + ld_c;
        cpa16(base,                         ga0);
        cpa16(base + 32 * TSTRIDE,          ga0 + 32 * lda);
        cpa16(base + TILE_B,                ga1);
        cpa16(base + TILE_B + 32 * TSTRIDE, ga1 + 32 * lda);
        cpa16(base + 2 * TILE_B,                gb0);
        cpa16(base + 2 * TILE_B + 32 * TSTRIDE, gb0 + 32 * ldb);
        cpa16(base + 3 * TILE_B,                gb1);
        cpa16(base + 3 * TILE_B + 32 * TSTRIDE, gb1 + 32 * ldb);
        cpa_commit();
    };

    issue(0, 0);
    for (int i = 0; i < nch; i++) {
        if (i + 1 < nch) { issue((i + 1) << 6, (i + 1) & 1); cpa_wait<1>(); }
        else             { cpa_wait<0>(); }
        __syncthreads();

        uint32_t st = sb + (i & 1) * STAGE_B;

        // prologue: fragments for ks = 0 into buffer 0
        {
            ldsm4(fbh[0][0][0], fbh[0][0][1], fbh[0][1][0], fbh[0][1][1], st + 2*TILE_B + boff);
            ldsm4(fbl[0][0][0], fbl[0][0][1], fbl[0][1][0], fbl[0][1][1], st + 3*TILE_B + boff);
#pragma unroll
            for (int mf = 0; mf < 2; mf++)
                ldsm4(fah[0][mf][0], fah[0][mf][1], fah[0][mf][2], fah[0][mf][3],
                      st + aoff + mf * (16*TSTRIDE));
#pragma unroll
            for (int mf = 0; mf < 2; mf++)
                ldsm4(fal[0][mf][0], fal[0][mf][1], fal[0][mf][2], fal[0][mf][3],
                      st + TILE_B + aoff + mf * (16*TSTRIDE));
        }

#pragma unroll
        for (int ks = 0; ks < 4; ks++) {
            const int cur = ks & 1, nxt = cur ^ 1;
            if (ks < 3) {                      // prefetch ks+1 while doing ks MMAs
                uint32_t kb = (ks + 1) * 32;
                ldsm4(fbh[nxt][0][0], fbh[nxt][0][1], fbh[nxt][1][0], fbh[nxt][1][1],
                      st + 2*TILE_B + boff + kb);
                ldsm4(fbl[nxt][0][0], fbl[nxt][0][1], fbl[nxt][1][0], fbl[nxt][1][1],
                      st + 3*TILE_B + boff + kb);
#pragma unroll
                for (int mf = 0; mf < 2; mf++)
                    ldsm4(fah[nxt][mf][0], fah[nxt][mf][1], fah[nxt][mf][2], fah[nxt][mf][3],
                          st + aoff + mf * (16*TSTRIDE) + kb);
#pragma unroll
                for (int mf = 0; mf < 2; mf++)
                    ldsm4(fal[nxt][mf][0], fal[nxt][mf][1], fal[nxt][mf][2], fal[nxt][mf][3],
                          st + TILE_B + aoff + mf * (16*TSTRIDE) + kb);
            }
#pragma unroll
            for (int mf = 0; mf < 2; mf++)
#pragma unroll
                for (int nf = 0; nf < 2; nf++) mma16816(acc[mf][nf], fah[cur][mf], fbh[cur][nf]);
#pragma unroll
            for (int mf = 0; mf < 2; mf++)
#pragma unroll
                for (int nf = 0; nf < 2; nf++) mma16816(acc[mf][nf], fah[cur][mf], fbl[cur][nf]);
#pragma unroll
            for (int mf = 0; mf < 2; mf++)
#pragma unroll
                for (int nf = 0; nf < 2; nf++) mma16816(acc[mf][nf], fal[cur][mf], fbh[cur][nf]);
        }
        __syncthreads();
    }

    // epilogue (registers -> gmem)
    const int g = lane >> 2, tg = lane & 3;
    const float* bp = bias ? bias + (long)z * bias_z : nullptr;
    float* Cz = C ? C + (long)z * c_z : nullptr;
#pragma unroll
    for (int mf = 0; mf < 2; mf++) {
#pragma unroll
        for (int nf = 0; nf < 2; nf++) {
            int row = m0 + wm * 32 + mf * 16 + g;
            int col = n0 + wn * 16 + nf * 8 + tg * 2;
            float v0 = acc[mf][nf][0], v1 = acc[mf][nf][1];
            float v2 = acc[mf][nf][2], v3 = acc[mf][nf][3];
            if (bp) {
                float bb0 = __ldg(bp + col), bb1 = __ldg(bp + col + 1);
                v0 += bb0; v1 += bb1; v2 += bb0; v3 += bb1;
            }
            if (flags & FL_RELU) {
                v0 = fmaxf(v0, 0.f); v1 = fmaxf(v1, 0.f);
                v2 = fmaxf(v2, 0.f); v3 = fmaxf(v3, 0.f);
            }
            if (flags & FL_F32) {
                *(float2*)&Cz[(long)row * ldc + col] = make_float2(v0, v1);
                *(float2*)&Cz[(long)(row + 8) * ldc + col] = make_float2(v2, v3);
            }
            if (flags & FL_HILO) {
                bf16 h0 = __float2bfloat16(v0), h1 = __float2bfloat16(v1);
                bf16 h2 = __float2bfloat16(v2), h3 = __float2bfloat16(v3);
                __nv_bfloat162 ph0; ph0.x = h0; ph0.y = h1;
                __nv_bfloat162 ph1; ph1.x = h2; ph1.y = h3;
                __nv_bfloat162 pl0, pl1;
                pl0.x = __float2bfloat16(v0 - __bfloat162float(h0));
                pl0.y = __float2bfloat16(v1 - __bfloat162float(h1));
                pl1.x = __float2bfloat16(v2 - __bfloat162float(h2));
                pl1.y = __float2bfloat16(v3 - __bfloat162float(h3));
                *(__nv_bfloat162*)&Ch[(long)row * ldch + col] = ph0;
                *(__nv_bfloat162*)&Cl[(long)row * ldch + col] = pl0;
                *(__nv_bfloat162*)&Ch[(long)(row + 8) * ldch + col] = ph1;
                *(__nv_bfloat162*)&Cl[(long)(row + 8) * ldch + col] = pl1;
            }
        }
    }
}

// ======================= LayerNorm 1 (writes bf16 hi/lo) =======================
__global__ void ln1_k(const float* __restrict__ in, const float* __restrict__ g,
                      const float* __restrict__ b, bf16* __restrict__ oh, bf16* __restrict__ ol)
{
    int row = blockIdx.x, t = threadIdx.x;   // 256 threads
    __shared__ float rbuf[256];
    long base = (long)row * DD;
    float v0 = in[base + t], v1 = in[base + t + 256];
    rbuf[t] = v0 + v1; __syncthreads();
    for (int s = 128; s > 0; s >>= 1) { if (t < s) rbuf[t] += rbuf[t + s]; __syncthreads(); }
    float mean = rbuf[0] * (1.0f / 512.0f);
    __syncthreads();
    float d0 = v0 - mean, d1 = v1 - mean;
    rbuf[t] = d0 * d0 + d1 * d1; __syncthreads();
    for (int s = 128; s > 0; s >>= 1) { if (t < s) rbuf[t] += rbuf[t + s]; __syncthreads(); }
    float rs = rsqrtf(rbuf[0] * (1.0f / 512.0f) + 1e-5f);
    float o0 = d0 * rs * g[t] + b[t];
    float o1 = d1 * rs * g[t + 256] + b[t + 256];
    bf16 h0 = __float2bfloat16(o0), h1 = __float2bfloat16(o1);
    oh[base + t] = h0;       ol[base + t]       = __float2bfloat16(o0 - __bfloat162float(h0));
    oh[base + t + 256] = h1; ol[base + t + 256] = __float2bfloat16(o1 - __bfloat162float(h1));
}

// ======================= LayerNorm 2 (residual, fp32 out) =======================
__global__ void ln2_k(const float* __restrict__ in, const float* __restrict__ add,
                      const float* __restrict__ g, const float* __restrict__ b,
                      float* __restrict__ out)
{
    int row = blockIdx.x, t = threadIdx.x;
    __shared__ float rbuf[256];
    long base = (long)row * DD;
    float v0 = in[base + t] + add[base + t];
    float v1 = in[base + t + 256] + add[base + t + 256];
    rbuf[t] = v0 + v1; __syncthreads();
    for (int s = 128; s > 0; s >>= 1) { if (t < s) rbuf[t] += rbuf[t + s]; __syncthreads(); }
    float mean = rbuf[0] * (1.0f / 512.0f);
    __syncthreads();
    float d0 = v0 - mean, d1 = v1 - mean;
    rbuf[t] = d0 * d0 + d1 * d1; __syncthreads();
    for (int s = 128; s > 0; s >>= 1) { if (t < s) rbuf[t] += rbuf[t + s]; __syncthreads(); }
    float rs = rsqrtf(rbuf[0] * (1.0f / 512.0f) + 1e-5f);
    out[base + t]       = d0 * rs * g[t]       + b[t];
    out[base + t + 256] = d1 * rs * g[t + 256] + b[t + 256];
}

// ======================= attention =======================
__global__ void attn_scores_k(const float* __restrict__ q, const float* __restrict__ k,
                              float* __restrict__ attn)
{
    int i = blockIdx.x, h = blockIdx.y, b = blockIdx.z, t = threadIdx.x; // 128 thr
    __shared__ float ks[SS][DH + 1];
    __shared__ float qs[DH];
    __shared__ float red[SS];
    const float* kbase = k + (long)b * SS * DD + h * DH;
    for (int idx = t; idx < SS * DH; idx += 128) {
        int j = idx >> 6, d = idx & 63;
        ks[j][d] = kbase[(long)j * DD + d];
    }
    if (t < DH) qs[t] = q[(long)(b * SS + i) * DD + h * DH + t];
    __syncthreads();
    float acc = 0.f;
#pragma unroll
    for (int d = 0; d < DH; d++) acc += qs[d] * ks[t][d];
    acc *= 0.125f;
    red[t] = acc; __syncthreads();
    for (int s = 64; s > 0; s >>= 1) { if (t < s) red[t] = fmaxf(red[t], red[t + s]); __syncthreads(); }
    float mx = red[0]; __syncthreads();
    float e = expf(acc - mx);
    red[t] = e; __syncthreads();
    for (int s = 64; s > 0; s >>= 1) { if (t < s) red[t] += red[t + s]; __syncthreads(); }
    attn[(((long)(b * HH + h) * SS) + i) * SS + t] = e / red[0];
}

__global__ void am_k(const float* __restrict__ attn, float* __restrict__ am)
{
    int bi = blockIdx.x;
    int b = bi >> 7, i = bi & 127, t = threadIdx.x;  // 128 thr
    float s = 0.f;
#pragma unroll
    for (int h = 0; h < HH; h++)
        s += attn[(((long)(b * HH + h) * SS) + i) * SS + t];
    am[(long)bi * SS + t] = s * 0.125f;
}

__global__ void attn_ctx_k(const float* __restrict__ attn, const float* __restrict__ v,
                           bf16* __restrict__ ch, bf16* __restrict__ cl)
{
    int i = blockIdx.x, h = blockIdx.y, b = blockIdx.z, t = threadIdx.x; // 64 thr
    __shared__ float at[SS];
    long arow = (((long)(b * HH + h) * SS) + i) * SS;
    at[t] = attn[arow + t]; at[t + 64] = attn[arow + t + 64];
    __syncthreads();
    float acc = 0.f;
    const float* vb = v + (long)b * SS * DD + h * DH + t;
#pragma unroll 8
    for (int j = 0; j < SS; j++) acc += at[j] * vb[(long)j * DD];
    long o = (long)(b * SS + i) * DD + h * DH + t;
    bf16 hh = __float2bfloat16(acc);
    ch[o] = hh; cl[o] = __float2bfloat16(acc - __bfloat162float(hh));
}

// ======================= nu: reduce split-K partials + bias + hi/lo =======================
__global__ void conv_nu_k(const float* __restrict__ P, const float* __restrict__ b2,
                          float* __restrict__ nu, bf16* __restrict__ H, bf16* __restrict__ L)
{
    int row = blockIdx.x, t = threadIdx.x;  // 256
    for (int c = t; c < DD; c += 256) {
        long i = (long)row * DD + c;
        float v = b2[c] + P[i] + P[UU + i] + P[2L*UU + i] + P[3L*UU + i];
        nu[i] = v;
        bf16 h = __float2bfloat16(v);
        H[i] = h; L[i] = __float2bfloat16(v - __bfloat162float(h));
    }
}

// ======================= pair relation classifier =======================
__global__ void pair_k(const float* __restrict__ ap, const float* __restrict__ bp,
                       const float* __restrict__ rc_b1, const float* __restrict__ rc_w2,
                       const float* __restrict__ rc_b2, const float* __restrict__ am,
                       int* __restrict__ rel)
{
    int b = blockIdx.z;
    int u0 = blockIdx.y * 16, v0 = blockIdx.x * 16;
    int t = threadIdx.x;                 // 256
    int ul = t >> 4, vl = t & 15;
    __shared__ float sA[16][65], sB[16][65], sW[64][8], sC[64];
    float acc[RR];
#pragma unroll
    for (int r = 0; r < RR; r++) acc[r] = rc_b2[r];

    for (int c0 = 0; c0 < DD; c0 += 64) {
        for (int idx = t; idx < 1024; idx += 256) {
            int rr = idx >> 6, cc = idx & 63;
            sA[rr][cc] = ap[(long)(b * SS + u0 + rr) * DD + c0 + cc];
            sB[rr][cc] = bp[(long)(b * SS + v0 + rr) * DD + c0 + cc];
        }
        for (int idx = t; idx < 512; idx += 256)
            sW[idx >> 3][idx & 7] = rc_w2[(long)(c0 + (idx >> 3)) * RR + (idx & 7)];
        if (t < 64) sC[t] = rc_b1[c0 + t];
        __syncthreads();
#pragma unroll 4
        for (int dd = 0; dd < 64; dd++) {
            float hsum = sA[ul][dd] + sB[vl][dd] + sC[dd];
            hsum = fmaxf(hsum, 0.f);
            float4 w0 = *(float4*)&sW[dd][0];
            float4 w1 = *(float4*)&sW[dd][4];
            acc[0] += hsum * w0.x; acc[1] += hsum * w0.y;
            acc[2] += hsum * w0.z; acc[3] += hsum * w0.w;
            acc[4] += hsum * w1.x; acc[5] += hsum * w1.y;
            acc[6] += hsum * w1.z; acc[7] += hsum * w1.w;
        }
        __syncthreads();
    }
    int pred = 0; float best = acc[0];
#pragma unroll
    for (int r = 1; r < RR; r++) if (acc[r] > best) { best = acc[r]; pred = r; }
    int u = u0 + ul, v = v0 + vl;
    float amv = am[((long)b * SS + u) * SS + v];
    int valid = (amv > THRESH) && (u != v) && (pred != 0);
    rel[((long)b * SS + u) * SS + v] = valid ? pred : 0;
}

// ======================= edge aggregation (writes reasoned hi/lo) =======================
__global__ void agg_k(const int* __restrict__ rel, const float* __restrict__ trans,
                      const float* __restrict__ nu, bf16* __restrict__ rh, bf16* __restrict__ rl)
{
    int bv = blockIdx.x;                 // b*S + v
    int b = bv >> 7, v = bv & 127, t = threadIdx.x;   // 256
    __shared__ int sr[SS];
    if (t < SS) sr[t] = rel[((long)b * SS + t) * SS + v];
    __syncthreads();
    float a0 = 0.f, a1 = 0.f;
    for (int u = 0; u < SS; u++) {
        int r = sr[u];
        if (r) {
            const float* tr = trans + ((long)(b * SS + u) * RR + r) * DD;
            a0 += tr[t]; a1 += tr[t + 256];
        }
    }
    long row = (long)bv * DD;
    float v0 = nu[row + t] + a0;
    float v1 = nu[row + t + 256] + a1;
    bf16 h0 = __float2bfloat16(v0), h1 = __float2bfloat16(v1);
    rh[row + t] = h0;       rl[row + t]       = __float2bfloat16(v0 - __bfloat162float(h0));
    rh[row + t + 256] = h1; rl[row + t + 256] = __float2bfloat16(v1 - __bfloat162float(h1));
}

// ======================= launch =======================
extern "C" void kernel_launch(void* const* d_in, const int* in_sizes, int n_in,
                              void* d_out, int out_size)
{
    const float* x     = (const float*)d_in[0];
    const float* ln1_g = (const float*)d_in[1];
    const float* ln1_b = (const float*)d_in[2];
    const float* wq    = (const float*)d_in[3];
    const float* bq    = (const float*)d_in[4];
    const float* wk    = (const float*)d_in[5];
    const float* bk    = (const float*)d_in[6];
    const float* wv    = (const float*)d_in[7];
    const float* bvv   = (const float*)d_in[8];
    const float* wo    = (const float*)d_in[9];
    const float* bo    = (const float*)d_in[10];
    const float* w1    = (const float*)d_in[11];
    const float* b1    = (const float*)d_in[12];
    const float* w2    = (const float*)d_in[13];
    const float* b2    = (const float*)d_in[14];
    const float* rc_w1 = (const float*)d_in[15];
    const float* rc_b1 = (const float*)d_in[16];
    const float* rc_w2 = (const float*)d_in[17];
    const float* rc_b2 = (const float*)d_in[18];
    const float* kg_w  = (const float*)d_in[19];
    const float* s2n_w = (const float*)d_in[20];
    const float* s2n_b = (const float*)d_in[21];
    const float* ln2_g = (const float*)d_in[22];
    const float* ln2_b = (const float*)d_in[23];
    float* out = (float*)d_out;

    bf16 *wTh, *wTl, *xnh, *xnl, *ctxh, *ctxl, *aoh, *aol, *hidh, *hidl, *nuh, *nul, *rsh, *rsl;
    float *b3, *qkv, *attn, *am, *nupart, *nu, *ab, *trans, *nr;
    int *rel;
    cudaGetSymbolAddress((void**)&wTh, g_wTh);   cudaGetSymbolAddress((void**)&wTl, g_wTl);
    cudaGetSymbolAddress((void**)&b3, g_b3);
    cudaGetSymbolAddress((void**)&xnh, g_xnh);   cudaGetSymbolAddress((void**)&xnl, g_xnl);
    cudaGetSymbolAddress((void**)&qkv, g_qkv);
    cudaGetSymbolAddress((void**)&attn, g_attn); cudaGetSymbolAddress((void**)&am, g_am);
    cudaGetSymbolAddress((void**)&ctxh, g_ctxh); cudaGetSymbolAddress((void**)&ctxl, g_ctxl);
    cudaGetSymbolAddress((void**)&aoh, g_aoh);   cudaGetSymbolAddress((void**)&aol, g_aol);
    cudaGetSymbolAddress((void**)&hidh, g_hidh); cudaGetSymbolAddress((void**)&hidl, g_hidl);
    cudaGetSymbolAddress((void**)&nupart, g_nupart);
    cudaGetSymbolAddress((void**)&nu, g_nu);
    cudaGetSymbolAddress((void**)&nuh, g_nuh);   cudaGetSymbolAddress((void**)&nul, g_nul);
    cudaGetSymbolAddress((void**)&ab, g_ab);
    cudaGetSymbolAddress((void**)&trans, g_trans);
    cudaGetSymbolAddress((void**)&rel, g_rel);
    cudaGetSymbolAddress((void**)&rsh, g_rsh);   cudaGetSymbolAddress((void**)&rsl, g_rsl);
    cudaGetSymbolAddress((void**)&nr, g_nr);

    cudaFuncSetAttribute(gemm_mma, cudaFuncAttributeMaxDynamicSharedMemorySize, GSM);
    cudaFuncSetAttribute(gemm_mma, cudaFuncAttributePreferredSharedMemoryCarveout, 100);

    // weight prep
    setup_k<<<1, 512>>>(wq, wk, wv, wo, w1, w2, rc_w1, kg_w, s2n_w, bq, bk, bvv);
    wconv_k<<<dim3(16, 16, 23), dim3(32, 8)>>>();

    // ln1 -> xn (hi/lo)
    ln1_k<<<BS, 256>>>(x, ln1_g, ln1_b, xnh, xnl);

    // QKV (z=3), fp32 out
    gemm_mma<<<dim3(8, 8, 3), 256, GSM>>>(xnh, xnl, DD, 0, wTh, wTl, UU, DD,
                                          b3, DD, qkv, UU, DD, nullptr, nullptr, 0,
                                          DD, FL_F32);
    // attention
    attn_scores_k<<<dim3(SS, HH, BB), 128>>>(qkv, qkv + UU, attn);
    am_k<<<BS, 128>>>(attn, am);
    attn_ctx_k<<<dim3(SS, HH, BB), 64>>>(attn, qkv + 2 * UU, ctxh, ctxl);

    // ao = ctx @ wo + bo  (hi/lo only)
    gemm_mma<<<dim3(8, 8, 1), 256, GSM>>>(ctxh, ctxl, DD, 0, wTh + 3L*UU, wTl + 3L*UU, 0, DD,
                                          bo, 0, nullptr, 0, 0, aoh, aol, DD,
                                          DD, FL_HILO);
    // hid = relu(ao @ w1 + b1) (hi/lo only, N=2048)
    gemm_mma<<<dim3(32, 8, 1), 256, GSM>>>(aoh, aol, DD, 0, wTh + 4L*UU, wTl + 4L*UU, 0, DD,
                                           b1, 0, nullptr, 0, 0, hidh, hidl, FF,
                                           DD, FL_HILO | FL_RELU);
    // nu partials = hid @ w2  (split-K z=4 into 4 slabs)
    gemm_mma<<<dim3(8, 8, 4), 256, GSM>>>(hidh, hidl, FF, DD, wTh + 8L*UU, wTl + 8L*UU, DD, FF,
                                          nullptr, 0, nupart, UU, DD, nullptr, nullptr, 0,
                                          DD, FL_F32);
    conv_nu_k<<<BS, 256>>>(nupart, b2, nu, nuh, nul);

    // a/b parts (z=2) and RGCN transforms (z=8), fp32
    gemm_mma<<<dim3(8, 8, 2), 256, GSM>>>(nuh, nul, DD, 0, wTh + 12L*UU, wTl + 12L*UU, UU, DD,
                                          nullptr, 0, ab, UU, DD, nullptr, nullptr, 0,
                                          DD, FL_F32);
    gemm_mma<<<dim3(8, 8, 8), 256, GSM>>>(nuh, nul, DD, 0, wTh + 14L*UU, wTl + 14L*UU, UU, DD,
                                          nullptr, 0, trans, DD, RR * DD, nullptr, nullptr, 0,
                                          DD, FL_F32);
    // edges + aggregation
    pair_k<<<dim3(8, 8, BB), 256>>>(ab, ab + UU, rc_b1, rc_w2, rc_b2, am, rel);
    agg_k<<<BS, 256>>>(rel, trans, nu, rsh, rsl);

    // s2n projection, fp32
    gemm_mma<<<dim3(8, 8, 1), 256, GSM>>>(rsh, rsl, DD, 0, wTh + 22L*UU, wTl + 22L*UU, 0, DD,
                                          s2n_b, 0, nr, 0, DD, nullptr, nullptr, 0,
                                          DD, FL_F32);
    // final residual LN
    ln2_k<<<BS, 256>>>(nr, x, ln2_g, ln2_b, out);
}

// round 6
// speedup vs baseline: 1.7053x; 1.1444x over previous
#include <cuda_runtime.h>
#include <cuda_bf16.h>
#include <math.h>
#include <stdint.h>

#define BB 4
#define SS 128
#define DD 512
#define HH 8
#define DH 64
#define FF 2048
#define RR 8
#define BS (BB*SS)          // 512
#define UU 262144           // 512*512
#define THRESH 0.1f

typedef __nv_bfloat16 bf16;

// ======================= helpers =======================
__device__ __forceinline__ uint32_t smem_u32(const void* p){
    uint32_t a;
    asm("{ .reg .u64 t; cvta.to.shared.u64 t, %1; cvt.u32.u64 %0, t; }" : "=r"(a) : "l"(p));
    return a;
}
__device__ __forceinline__ void ldsm4(uint32_t& r0, uint32_t& r1, uint32_t& r2, uint32_t& r3,
                                      uint32_t addr){
    asm volatile("ldmatrix.sync.aligned.m8n8.x4.shared.b16 {%0,%1,%2,%3}, [%4];"
                 : "=r"(r0), "=r"(r1), "=r"(r2), "=r"(r3) : "r"(addr));
}
__device__ __forceinline__ void mma16816(float* d, const uint32_t* a, const uint32_t* b){
    asm volatile("mma.sync.aligned.m16n8k16.row.col.f32.bf16.bf16.f32 "
                 "{%0,%1,%2,%3}, {%4,%5,%6,%7}, {%8,%9}, {%0,%1,%2,%3};"
                 : "+f"(d[0]), "+f"(d[1]), "+f"(d[2]), "+f"(d[3])
                 : "r"(a[0]), "r"(a[1]), "r"(a[2]), "r"(a[3]), "r"(b[0]), "r"(b[1]));
}
__device__ __forceinline__ void cpa16(uint32_t s, const void* g){
    asm volatile("cp.async.cg.shared.global [%0], [%1], 16;" :: "r"(s), "l"(g));
}
__device__ __forceinline__ void cpa_commit(){
    asm volatile("cp.async.commit_group;" ::: "memory");
}
template<int N> __device__ __forceinline__ void cpa_wait(){
    asm volatile("cp.async.wait_group %0;" :: "n"(N) : "memory");
}

// ======================= scratch (device globals) =======================
__device__ bf16  g_wTh[23*UU];          // packed transposed weights, hi
__device__ bf16  g_wTl[23*UU];          // packed transposed weights, lo
__device__ float g_b3[3*DD];            // packed q/k/v biases
__device__ bf16  g_xnh[UU], g_xnl[UU];
__device__ float g_qkv[3*UU];
__device__ float g_attn[BB*HH*SS*SS];
__device__ float g_am[BB*SS*SS];
__device__ bf16  g_ctxh[UU], g_ctxl[UU];
__device__ bf16  g_aoh[UU],  g_aol[UU];
__device__ bf16  g_hidh[BS*FF], g_hidl[BS*FF];
__device__ float g_nupart[4*UU];        // split-K partials for nu
__device__ float g_nu[UU];
__device__ bf16  g_nuh[UU], g_nul[UU];
__device__ float g_abt[10*UU];          // [0,1]=a/b parts, [2..9]=trans slabs [r][n][d]
__device__ int   g_rel[BB*SS*SS];
__device__ bf16  g_rsh[UU], g_rsl[UU];
__device__ float g_nr[UU];

struct WUnit { const float* src; int ld; long dst; int dld; };
__device__ WUnit g_wu[23];

// ======================= setup: weight-unit table + packed biases =======================
__global__ void setup_k(const float* wq, const float* wk, const float* wv, const float* wo,
                        const float* w1, const float* w2, const float* rc, const float* kg,
                        const float* s2n, const float* bq, const float* bk, const float* bvv)
{
    int t = threadIdx.x;
    if (t < DD) { g_b3[t] = bq[t]; g_b3[DD+t] = bk[t]; g_b3[2*DD+t] = bvv[t]; }
    if (t == 0) {
        const float* qkv[3] = {wq, wk, wv};
        for (int u = 0; u < 3; u++) g_wu[u] = {qkv[u], DD, (long)u*UU, DD};
        g_wu[3] = {wo, DD, 3L*UU, DD};
        for (int u = 0; u < 4; u++)                       // w1 [512][2048] -> [2048][512]
            g_wu[4+u] = {w1 + u*DD, FF, 4L*UU + (long)u*UU, DD};
        for (int u = 0; u < 4; u++)                       // w2 [2048][512] -> [512][2048]
            g_wu[8+u] = {w2 + (long)u*UU, DD, 8L*UU + (long)u*DD, FF};
        for (int u = 0; u < 2; u++)
            g_wu[12+u] = {rc + (long)u*UU, DD, (12L+u)*UU, DD};
        for (int u = 0; u < 8; u++)
            g_wu[14+u] = {kg + (long)u*UU, DD, (14L+u)*UU, DD};
        g_wu[22] = {s2n, DD, 22L*UU, DD};
    }
}

// ======================= weight transpose + fp32 -> bf16 hi/lo =======================
__global__ void wconv_k()
{
    __shared__ float tile[32][33];
    WUnit u = g_wu[blockIdx.z];
    int k0 = blockIdx.y * 32, n0 = blockIdx.x * 32;
    int tx = threadIdx.x, ty = threadIdx.y;        // (32, 8)
#pragma unroll
    for (int i = 0; i < 4; i++)
        tile[ty + 8*i][tx] = __ldg(u.src + (long)(k0 + ty + 8*i) * u.ld + n0 + tx);
    __syncthreads();
#pragma unroll
    for (int i = 0; i < 4; i++) {
        int n = n0 + ty + 8*i, k = k0 + tx;
        float v = tile[tx][ty + 8*i];
        bf16 h = __float2bfloat16(v);
        bf16 l = __float2bfloat16(v - __bfloat162float(h));
        long off = u.dst + (long)n * u.dld + k;
        g_wTh[off] = h; g_wTl[off] = l;
    }
}

// ======================= mma.sync bf16 3-pass GEMM, cp.async 3-stage =======================
#define FL_F32  1
#define FL_HILO 2
#define FL_RELU 4

#define TSTRIDE 144                      // smem row stride bytes (72 bf16)
#define TILE_B  9216                     // 64 rows * 144 B
#define STAGE_B 36864                    // 4 tiles
#define GSM     110592                   // 3 stages

__global__ void __launch_bounds__(256, 2)
gemm_mma(const bf16* __restrict__ Ah, const bf16* __restrict__ Al, int lda, long a_z,
         const bf16* __restrict__ Bh, const bf16* __restrict__ Bl, long b_z, int ldb,
         const float* __restrict__ bias, int bias_z,
         float* __restrict__ C, long c_z, int ldc,
         bf16* __restrict__ Ch, bf16* __restrict__ Cl, int ldch,
         int K, int flags)
{
    extern __shared__ char sm[];
    uint32_t sb = smem_u32(sm);
    const int tid = threadIdx.x, lane = tid & 31, wid = tid >> 5;
    const int wm = wid >> 2, wn = wid & 3;               // warp grid 2 x 4
    const int m0 = blockIdx.y * 64, n0 = blockIdx.x * 64, z = blockIdx.z;
    const bf16* Ahp = Ah + (long)z * a_z;
    const bf16* Alp = Al + (long)z * a_z;
    const bf16* Bhp = Bh + (long)z * b_z;
    const bf16* Blp = Bl + (long)z * b_z;

    const int ld_r = tid >> 3, ld_c = (tid & 7) * 8;
    const uint32_t s_wr = (uint32_t)(ld_r * TSTRIDE + ld_c * 2);

    const int a_r = (lane & 7) + ((lane >> 3) & 1) * 8;
    const int a_c8 = (lane >> 4) * 8;
    const uint32_t aoff = (uint32_t)((wm * 32 + a_r) * TSTRIDE + a_c8 * 2);
    const int b_r = (lane & 7) + (lane >> 4) * 8;
    const int b_c8 = ((lane >> 3) & 1) * 8;
    const uint32_t boff = (uint32_t)((wn * 16 + b_r) * TSTRIDE + b_c8 * 2);

    float acc[2][2][4];
#pragma unroll
    for (int i = 0; i < 2; i++)
#pragma unroll
        for (int j = 0; j < 2; j++)
#pragma unroll
            for (int q = 0; q < 4; q++) acc[i][j][q] = 0.f;

    uint32_t fah[2][2][4], fal[2][2][4], fbh[2][2][2], fbl[2][2][2];

    const int nch = K >> 6;

    auto issue = [&](int kk, int st){
        uint32_t base = sb + st * STAGE_B + s_wr;
        const bf16* ga0 = Ahp + (long)(m0 + ld_r) * lda + kk + ld_c;
        const bf16* ga1 = Alp + (long)(m0 + ld_r) * lda + kk + ld_c;
        const bf16* gb0 = Bhp + (long)(n0 + ld_r) * ldb + kk + ld_c;
        const bf16* gb1 = Blp + (long)(n0 + ld_r) * ldb + kk + ld_c;
        cpa16(base,                         ga0);
        cpa16(base + 32 * TSTRIDE,          ga0 + 32 * lda);
        cpa16(base + TILE_B,                ga1);
        cpa16(base + TILE_B + 32 * TSTRIDE, ga1 + 32 * lda);
        cpa16(base + 2 * TILE_B,                gb0);
        cpa16(base + 2 * TILE_B + 32 * TSTRIDE, gb0 + 32 * ldb);
        cpa16(base + 3 * TILE_B,                gb1);
        cpa16(base + 3 * TILE_B + 32 * TSTRIDE, gb1 + 32 * ldb);
        cpa_commit();
    };

    issue(0, 0);
    if (nch > 1) issue(64, 1);
    for (int i = 0; i < nch; i++) {
        if (i + 2 < nch) issue((i + 2) << 6, (i + 2) % 3);
        int rem = nch - 1 - i;
        if (rem >= 2)      cpa_wait<2>();
        else if (rem == 1) cpa_wait<1>();
        else               cpa_wait<0>();
        __syncthreads();

        uint32_t st = sb + (i % 3) * STAGE_B;

        // prologue fragments for ks=0
        {
            ldsm4(fbh[0][0][0], fbh[0][0][1], fbh[0][1][0], fbh[0][1][1], st + 2*TILE_B + boff);
            ldsm4(fbl[0][0][0], fbl[0][0][1], fbl[0][1][0], fbl[0][1][1], st + 3*TILE_B + boff);
#pragma unroll
            for (int mf = 0; mf < 2; mf++)
                ldsm4(fah[0][mf][0], fah[0][mf][1], fah[0][mf][2], fah[0][mf][3],
                      st + aoff + mf * (16*TSTRIDE));
#pragma unroll
            for (int mf = 0; mf < 2; mf++)
                ldsm4(fal[0][mf][0], fal[0][mf][1], fal[0][mf][2], fal[0][mf][3],
                      st + TILE_B + aoff + mf * (16*TSTRIDE));
        }

#pragma unroll
        for (int ks = 0; ks < 4; ks++) {
            const int cur = ks & 1, nxt = cur ^ 1;
            if (ks < 3) {
                uint32_t kb = (ks + 1) * 32;
                ldsm4(fbh[nxt][0][0], fbh[nxt][0][1], fbh[nxt][1][0], fbh[nxt][1][1],
                      st + 2*TILE_B + boff + kb);
                ldsm4(fbl[nxt][0][0], fbl[nxt][0][1], fbl[nxt][1][0], fbl[nxt][1][1],
                      st + 3*TILE_B + boff + kb);
#pragma unroll
                for (int mf = 0; mf < 2; mf++)
                    ldsm4(fah[nxt][mf][0], fah[nxt][mf][1], fah[nxt][mf][2], fah[nxt][mf][3],
                          st + aoff + mf * (16*TSTRIDE) + kb);
#pragma unroll
                for (int mf = 0; mf < 2; mf++)
                    ldsm4(fal[nxt][mf][0], fal[nxt][mf][1], fal[nxt][mf][2], fal[nxt][mf][3],
                          st + TILE_B + aoff + mf * (16*TSTRIDE) + kb);
            }
#pragma unroll
            for (int mf = 0; mf < 2; mf++)
#pragma unroll
                for (int nf = 0; nf < 2; nf++) mma16816(acc[mf][nf], fah[cur][mf], fbh[cur][nf]);
#pragma unroll
            for (int mf = 0; mf < 2; mf++)
#pragma unroll
                for (int nf = 0; nf < 2; nf++) mma16816(acc[mf][nf], fah[cur][mf], fbl[cur][nf]);
#pragma unroll
            for (int mf = 0; mf < 2; mf++)
#pragma unroll
                for (int nf = 0; nf < 2; nf++) mma16816(acc[mf][nf], fal[cur][mf], fbh[cur][nf]);
        }
        __syncthreads();
    }

    // epilogue
    const int g = lane >> 2, tg = lane & 3;
    const float* bp = bias ? bias + (long)z * bias_z : nullptr;
    float* Cz = C ? C + (long)z * c_z : nullptr;
#pragma unroll
    for (int mf = 0; mf < 2; mf++) {
#pragma unroll
        for (int nf = 0; nf < 2; nf++) {
            int row = m0 + wm * 32 + mf * 16 + g;
            int col = n0 + wn * 16 + nf * 8 + tg * 2;
            float v0 = acc[mf][nf][0], v1 = acc[mf][nf][1];
            float v2 = acc[mf][nf][2], v3 = acc[mf][nf][3];
            if (bp) {
                float bb0 = __ldg(bp + col), bb1 = __ldg(bp + col + 1);
                v0 += bb0; v1 += bb1; v2 += bb0; v3 += bb1;
            }
            if (flags & FL_RELU) {
                v0 = fmaxf(v0, 0.f); v1 = fmaxf(v1, 0.f);
                v2 = fmaxf(v2, 0.f); v3 = fmaxf(v3, 0.f);
            }
            if (flags & FL_F32) {
                *(float2*)&Cz[(long)row * ldc + col] = make_float2(v0, v1);
                *(float2*)&Cz[(long)(row + 8) * ldc + col] = make_float2(v2, v3);
            }
            if (flags & FL_HILO) {
                bf16 h0 = __float2bfloat16(v0), h1 = __float2bfloat16(v1);
                bf16 h2 = __float2bfloat16(v2), h3 = __float2bfloat16(v3);
                __nv_bfloat162 ph0; ph0.x = h0; ph0.y = h1;
                __nv_bfloat162 ph1; ph1.x = h2; ph1.y = h3;
                __nv_bfloat162 pl0, pl1;
                pl0.x = __float2bfloat16(v0 - __bfloat162float(h0));
                pl0.y = __float2bfloat16(v1 - __bfloat162float(h1));
                pl1.x = __float2bfloat16(v2 - __bfloat162float(h2));
                pl1.y = __float2bfloat16(v3 - __bfloat162float(h3));
                *(__nv_bfloat162*)&Ch[(long)row * ldch + col] = ph0;
                *(__nv_bfloat162*)&Cl[(long)row * ldch + col] = pl0;
                *(__nv_bfloat162*)&Ch[(long)(row + 8) * ldch + col] = ph1;
                *(__nv_bfloat162*)&Cl[(long)(row + 8) * ldch + col] = pl1;
            }
        }
    }
}

// ======================= LayerNorms =======================
__global__ void ln1_k(const float* __restrict__ in, const float* __restrict__ g,
                      const float* __restrict__ b, bf16* __restrict__ oh, bf16* __restrict__ ol)
{
    int row = blockIdx.x, t = threadIdx.x;   // 256 threads
    __shared__ float rbuf[256];
    long base = (long)row * DD;
    float v0 = in[base + t], v1 = in[base + t + 256];
    rbuf[t] = v0 + v1; __syncthreads();
    for (int s = 128; s > 0; s >>= 1) { if (t < s) rbuf[t] += rbuf[t + s]; __syncthreads(); }
    float mean = rbuf[0] * (1.0f / 512.0f);
    __syncthreads();
    float d0 = v0 - mean, d1 = v1 - mean;
    rbuf[t] = d0 * d0 + d1 * d1; __syncthreads();
    for (int s = 128; s > 0; s >>= 1) { if (t < s) rbuf[t] += rbuf[t + s]; __syncthreads(); }
    float rs = rsqrtf(rbuf[0] * (1.0f / 512.0f) + 1e-5f);
    float o0 = d0 * rs * g[t] + b[t];
    float o1 = d1 * rs * g[t + 256] + b[t + 256];
    bf16 h0 = __float2bfloat16(o0), h1 = __float2bfloat16(o1);
    oh[base + t] = h0;       ol[base + t]       = __float2bfloat16(o0 - __bfloat162float(h0));
    oh[base + t + 256] = h1; ol[base + t + 256] = __float2bfloat16(o1 - __bfloat162float(h1));
}

__global__ void ln2_k(const float* __restrict__ in, const float* __restrict__ add,
                      const float* __restrict__ g, const float* __restrict__ b,
                      float* __restrict__ out)
{
    int row = blockIdx.x, t = threadIdx.x;
    __shared__ float rbuf[256];
    long base = (long)row * DD;
    float v0 = in[base + t] + add[base + t];
    float v1 = in[base + t + 256] + add[base + t + 256];
    rbuf[t] = v0 + v1; __syncthreads();
    for (int s = 128; s > 0; s >>= 1) { if (t < s) rbuf[t] += rbuf[t + s]; __syncthreads(); }
    float mean = rbuf[0] * (1.0f / 512.0f);
    __syncthreads();
    float d0 = v0 - mean, d1 = v1 - mean;
    rbuf[t] = d0 * d0 + d1 * d1; __syncthreads();
    for (int s = 128; s > 0; s >>= 1) { if (t < s) rbuf[t] += rbuf[t + s]; __syncthreads(); }
    float rs = rsqrtf(rbuf[0] * (1.0f / 512.0f) + 1e-5f);
    out[base + t]       = d0 * rs * g[t]       + b[t];
    out[base + t + 256] = d1 * rs * g[t + 256] + b[t + 256];
}

// ======================= attention: scores+softmax, 16-row tiles =======================
__global__ void attn_scores_k(const float* __restrict__ q, const float* __restrict__ k,
                              float* __restrict__ attn)
{
    int it = blockIdx.x, h = blockIdx.y, b = blockIdx.z;  // 256 thr
    int t = threadIdx.x;
    int i0 = it * 16;
    __shared__ float ks[SS][DH + 1];
    __shared__ float qs[16][DH + 1];
    __shared__ float P[16][SS];
    const float* kbase = k + (long)b * SS * DD + h * DH;
    const float* qbase = q + (long)b * SS * DD + h * DH;
    for (int idx = t; idx < SS * DH; idx += 256) {
        int j = idx >> 6, d = idx & 63;
        ks[j][d] = kbase[(long)j * DD + d];
    }
    for (int idx = t; idx < 16 * DH; idx += 256) {
        int r = idx >> 6, d = idx & 63;
        qs[r][d] = qbase[(long)(i0 + r) * DD + d];
    }
    __syncthreads();
    // scores: thread (grp = t>>7 in {0,1}, j = t&127) computes rows grp*8 + 0..7
    {
        int j = t & 127, grp = t >> 7;
#pragma unroll
        for (int r = 0; r < 8; r++) {
            int i = grp * 8 + r;
            float acc = 0.f;
#pragma unroll
            for (int d = 0; d < DH; d++) acc += qs[i][d] * ks[j][d];
            P[i][j] = acc * 0.125f;
        }
    }
    __syncthreads();
    // softmax: warp w handles rows 2w, 2w+1
    {
        int w = t >> 5, ln = t & 31;
        long obase = (((long)(b * HH + h) * SS) + i0) * SS;
#pragma unroll
        for (int rr = 0; rr < 2; rr++) {
            int i = w * 2 + rr;
            float m = -1e30f;
#pragma unroll
            for (int c = 0; c < 4; c++) m = fmaxf(m, P[i][ln + c * 32]);
#pragma unroll
            for (int o = 16; o > 0; o >>= 1) m = fmaxf(m, __shfl_xor_sync(0xffffffffu, m, o));
            float s = 0.f, e[4];
#pragma unroll
            for (int c = 0; c < 4; c++) { e[c] = expf(P[i][ln + c * 32] - m); s += e[c]; }
#pragma unroll
            for (int o = 16; o > 0; o >>= 1) s += __shfl_xor_sync(0xffffffffu, s, o);
            float inv = 1.0f / s;
#pragma unroll
            for (int c = 0; c < 4; c++) attn[obase + (long)i * SS + ln + c * 32] = e[c] * inv;
        }
    }
}

__global__ void am_k(const float* __restrict__ attn, float* __restrict__ am)
{
    int bi = blockIdx.x;
    int b = bi >> 7, i = bi & 127, t = threadIdx.x;  // 128 thr
    float s = 0.f;
#pragma unroll
    for (int h = 0; h < HH; h++)
        s += attn[(((long)(b * HH + h) * SS) + i) * SS + t];
    am[(long)bi * SS + t] = s * 0.125f;
}

// ======================= attention: ctx = P @ V, 16-row tiles =======================
__global__ void attn_ctx_k(const float* __restrict__ attn, const float* __restrict__ v,
                           bf16* __restrict__ ch, bf16* __restrict__ cl)
{
    int it = blockIdx.x, h = blockIdx.y, b = blockIdx.z;  // 256 thr
    int t = threadIdx.x;
    int i0 = it * 16;
    int d = t & 63, ig = t >> 6;          // ig in 0..3; rows i = ig + 4*r
    __shared__ float vs[SS][DH + 1];
    __shared__ float at[16][SS];
    const float* vbase = v + (long)b * SS * DD + h * DH;
    for (int idx = t; idx < SS * DH; idx += 256) {
        int j = idx >> 6, dd = idx & 63;
        vs[j][dd] = vbase[(long)j * DD + dd];
    }
    long arow = (((long)(b * HH + h) * SS) + i0) * SS;
    for (int idx = t; idx < 16 * SS; idx += 256)
        at[idx >> 7][idx & 127] = attn[arow + (long)(idx >> 7) * SS + (idx & 127)];
    __syncthreads();

    float acc[4] = {0.f, 0.f, 0.f, 0.f};
#pragma unroll
    for (int jh = 0; jh < 2; jh++) {
        float vreg[64];
#pragma unroll
        for (int jj = 0; jj < 64; jj++) vreg[jj] = vs[jh * 64 + jj][d];
#pragma unroll
        for (int r = 0; r < 4; r++) {
            int i = ig + 4 * r;
            float a = acc[r];
#pragma unroll
            for (int jj = 0; jj < 64; jj++) a += at[i][jh * 64 + jj] * vreg[jj];
            acc[r] = a;
        }
    }
#pragma unroll
    for (int r = 0; r < 4; r++) {
        int i = ig + 4 * r;
        long o = (long)(b * SS + i0 + i) * DD + h * DH + d;
        bf16 hh = __float2bfloat16(acc[r]);
        ch[o] = hh; cl[o] = __float2bfloat16(acc[r] - __bfloat162float(hh));
    }
}

// ======================= nu: reduce split-K partials + bias + hi/lo =======================
__global__ void conv_nu_k(const float* __restrict__ P, const float* __restrict__ b2,
                          float* __restrict__ nu, bf16* __restrict__ H, bf16* __restrict__ L)
{
    int row = blockIdx.x, t = threadIdx.x;  // 256
    for (int c = t; c < DD; c += 256) {
        long i = (long)row * DD + c;
        float v = b2[c] + P[i] + P[UU + i] + P[2L*UU + i] + P[3L*UU + i];
        nu[i] = v;
        bf16 h = __float2bfloat16(v);
        H[i] = h; L[i] = __float2bfloat16(v - __bfloat162float(h));
    }
}

// ======================= pair relation classifier =======================
__global__ void pair_k(const float* __restrict__ ap, const float* __restrict__ bp,
                       const float* __restrict__ rc_b1, const float* __restrict__ rc_w2,
                       const float* __restrict__ rc_b2, const float* __restrict__ am,
                       int* __restrict__ rel)
{
    int b = blockIdx.z;
    int u0 = blockIdx.y * 16, v0 = blockIdx.x * 16;
    int t = threadIdx.x;                 // 256
    int ul = t >> 4, vl = t & 15;
    __shared__ float sA[16][65], sB[16][65], sW[64][8], sC[64];
    float acc[RR];
#pragma unroll
    for (int r = 0; r < RR; r++) acc[r] = rc_b2[r];

    for (int c0 = 0; c0 < DD; c0 += 64) {
        for (int idx = t; idx < 1024; idx += 256) {
            int rr = idx >> 6, cc = idx & 63;
            sA[rr][cc] = ap[(long)(b * SS + u0 + rr) * DD + c0 + cc];
            sB[rr][cc] = bp[(long)(b * SS + v0 + rr) * DD + c0 + cc];
        }
        for (int idx = t; idx < 512; idx += 256)
            sW[idx >> 3][idx & 7] = rc_w2[(long)(c0 + (idx >> 3)) * RR + (idx & 7)];
        if (t < 64) sC[t] = rc_b1[c0 + t];
        __syncthreads();
#pragma unroll 4
        for (int dd = 0; dd < 64; dd++) {
            float hsum = sA[ul][dd] + sB[vl][dd] + sC[dd];
            hsum = fmaxf(hsum, 0.f);
            float4 w0 = *(float4*)&sW[dd][0];
            float4 w1 = *(float4*)&sW[dd][4];
            acc[0] += hsum * w0.x; acc[1] += hsum * w0.y;
            acc[2] += hsum * w0.z; acc[3] += hsum * w0.w;
            acc[4] += hsum * w1.x; acc[5] += hsum * w1.y;
            acc[6] += hsum * w1.z; acc[7] += hsum * w1.w;
        }
        __syncthreads();
    }
    int pred = 0; float best = acc[0];
#pragma unroll
    for (int r = 1; r < RR; r++) if (acc[r] > best) { best = acc[r]; pred = r; }
    int u = u0 + ul, v = v0 + vl;
    float amv = am[((long)b * SS + u) * SS + v];
    int valid = (amv > THRESH) && (u != v) && (pred != 0);
    rel[((long)b * SS + u) * SS + v] = valid ? pred : 0;
}

// ======================= edge aggregation (trans slabs [r][n][d]) =======================
__global__ void agg_k(const int* __restrict__ rel, const float* __restrict__ trans,
                      const float* __restrict__ nu, bf16* __restrict__ rh, bf16* __restrict__ rl)
{
    int bv = blockIdx.x;                 // b*S + v
    int b = bv >> 7, v = bv & 127, t = threadIdx.x;   // 256
    __shared__ int sr[SS];
    if (t < SS) sr[t] = rel[((long)b * SS + t) * SS + v];
    __syncthreads();
    float a0 = 0.f, a1 = 0.f;
    for (int u = 0; u < SS; u++) {
        int r = sr[u];
        if (r) {
            const float* tr = trans + (long)r * UU + (long)(b * SS + u) * DD;
            a0 += tr[t]; a1 += tr[t + 256];
        }
    }
    long row = (long)bv * DD;
    float v0 = nu[row + t] + a0;
    float v1 = nu[row + t + 256] + a1;
    bf16 h0 = __float2bfloat16(v0), h1 = __float2bfloat16(v1);
    rh[row + t] = h0;       rl[row + t]       = __float2bfloat16(v0 - __bfloat162float(h0));
    rh[row + t + 256] = h1; rl[row + t + 256] = __float2bfloat16(v1 - __bfloat162float(h1));
}

// ======================= launch =======================
extern "C" void kernel_launch(void* const* d_in, const int* in_sizes, int n_in,
                              void* d_out, int out_size)
{
    const float* x     = (const float*)d_in[0];
    const float* ln1_g = (const float*)d_in[1];
    const float* ln1_b = (const float*)d_in[2];
    const float* wq    = (const float*)d_in[3];
    const float* bq    = (const float*)d_in[4];
    const float* wk    = (const float*)d_in[5];
    const float* bk    = (const float*)d_in[6];
    const float* wv    = (const float*)d_in[7];
    const float* bvv   = (const float*)d_in[8];
    const float* wo    = (const float*)d_in[9];
    const float* bo    = (const float*)d_in[10];
    const float* w1    = (const float*)d_in[11];
    const float* b1    = (const float*)d_in[12];
    const float* w2    = (const float*)d_in[13];
    const float* b2    = (const float*)d_in[14];
    const float* rc_w1 = (const float*)d_in[15];
    const float* rc_b1 = (const float*)d_in[16];
    const float* rc_w2 = (const float*)d_in[17];
    const float* rc_b2 = (const float*)d_in[18];
    const float* kg_w  = (const float*)d_in[19];
    const float* s2n_w = (const float*)d_in[20];
    const float* s2n_b = (const float*)d_in[21];
    const float* ln2_g = (const float*)d_in[22];
    const float* ln2_b = (const float*)d_in[23];
    float* out = (float*)d_out;

    bf16 *wTh, *wTl, *xnh, *xnl, *ctxh, *ctxl, *aoh, *aol, *hidh, *hidl, *nuh, *nul, *rsh, *rsl;
    float *b3, *qkv, *attn, *am, *nupart, *nu, *abt, *nr;
    int *rel;
    cudaGetSymbolAddress((void**)&wTh, g_wTh);   cudaGetSymbolAddress((void**)&wTl, g_wTl);
    cudaGetSymbolAddress((void**)&b3, g_b3);
    cudaGetSymbolAddress((void**)&xnh, g_xnh);   cudaGetSymbolAddress((void**)&xnl, g_xnl);
    cudaGetSymbolAddress((void**)&qkv, g_qkv);
    cudaGetSymbolAddress((void**)&attn, g_attn); cudaGetSymbolAddress((void**)&am, g_am);
    cudaGetSymbolAddress((void**)&ctxh, g_ctxh); cudaGetSymbolAddress((void**)&ctxl, g_ctxl);
    cudaGetSymbolAddress((void**)&aoh, g_aoh);   cudaGetSymbolAddress((void**)&aol, g_aol);
    cudaGetSymbolAddress((void**)&hidh, g_hidh); cudaGetSymbolAddress((void**)&hidl, g_hidl);
    cudaGetSymbolAddress((void**)&nupart, g_nupart);
    cudaGetSymbolAddress((void**)&nu, g_nu);
    cudaGetSymbolAddress((void**)&nuh, g_nuh);   cudaGetSymbolAddress((void**)&nul, g_nul);
    cudaGetSymbolAddress((void**)&abt, g_abt);
    cudaGetSymbolAddress((void**)&rel, g_rel);
    cudaGetSymbolAddress((void**)&rsh, g_rsh);   cudaGetSymbolAddress((void**)&rsl, g_rsl);
    cudaGetSymbolAddress((void**)&nr, g_nr);

    cudaFuncSetAttribute(gemm_mma, cudaFuncAttributeMaxDynamicSharedMemorySize, GSM);
    cudaFuncSetAttribute(gemm_mma, cudaFuncAttributePreferredSharedMemoryCarveout, 100);

    // weight prep
    setup_k<<<1, 512>>>(wq, wk, wv, wo, w1, w2, rc_w1, kg_w, s2n_w, bq, bk, bvv);
    wconv_k<<<dim3(16, 16, 23), dim3(32, 8)>>>();

    // ln1 -> xn (hi/lo)
    ln1_k<<<BS, 256>>>(x, ln1_g, ln1_b, xnh, xnl);

    // QKV (z=3), fp32 out
    gemm_mma<<<dim3(8, 8, 3), 256, GSM>>>(xnh, xnl, DD, 0, wTh, wTl, UU, DD,
                                          b3, DD, qkv, UU, DD, nullptr, nullptr, 0,
                                          DD, FL_F32);
    // attention (16-row tiled)
    attn_scores_k<<<dim3(8, HH, BB), 256>>>(qkv, qkv + UU, attn);
    am_k<<<BS, 128>>>(attn, am);
    attn_ctx_k<<<dim3(8, HH, BB), 256>>>(attn, qkv + 2 * UU, ctxh, ctxl);

    // ao = ctx @ wo + bo  (hi/lo only)
    gemm_mma<<<dim3(8, 8, 1), 256, GSM>>>(ctxh, ctxl, DD, 0, wTh + 3L*UU, wTl + 3L*UU, 0, DD,
                                          bo, 0, nullptr, 0, 0, aoh, aol, DD,
                                          DD, FL_HILO);
    // hid = relu(ao @ w1 + b1) (hi/lo only, N=2048)
    gemm_mma<<<dim3(32, 8, 1), 256, GSM>>>(aoh, aol, DD, 0, wTh + 4L*UU, wTl + 4L*UU, 0, DD,
                                           b1, 0, nullptr, 0, 0, hidh, hidl, FF,
                                           DD, FL_HILO | FL_RELU);
    // nu partials = hid @ w2  (split-K z=4 into 4 slabs)
    gemm_mma<<<dim3(8, 8, 4), 256, GSM>>>(hidh, hidl, FF, DD, wTh + 8L*UU, wTl + 8L*UU, DD, FF,
                                          nullptr, 0, nupart, UU, DD, nullptr, nullptr, 0,
                                          DD, FL_F32);
    conv_nu_k<<<BS, 256>>>(nupart, b2, nu, nuh, nul);

    // fused: a/b parts (z=0,1) + RGCN transforms (z=2..9) in one launch
    gemm_mma<<<dim3(8, 8, 10), 256, GSM>>>(nuh, nul, DD, 0, wTh + 12L*UU, wTl + 12L*UU, UU, DD,
                                           nullptr, 0, abt, UU, DD, nullptr, nullptr, 0,
                                           DD, FL_F32);
    // edges + aggregation (trans slabs start at abt + 2*UU)
    pair_k<<<dim3(8, 8, BB), 256>>>(abt, abt + UU, rc_b1, rc_w2, rc_b2, am, rel);
    agg_k<<<BS, 256>>>(rel, abt + 2L*UU, nu, rsh, rsl);

    // s2n projection, fp32
    gemm_mma<<<dim3(8, 8, 1), 256, GSM>>>(rsh, rsl, DD, 0, wTh + 22L*UU, wTl + 22L*UU, 0, DD,
                                          s2n_b, 0, nr, 0, DD, nullptr, nullptr, 0,
                                          DD, FL_F32);
    // final residual LN
    ln2_k<<<BS, 256>>>(nr, x, ln2_g, ln2_b, out);
}

// round 7
// speedup vs baseline: 1.7242x; 1.0111x over previous
#include <cuda_runtime.h>
#include <cuda_bf16.h>
#include <math.h>
#include <stdint.h>

#define BB 4
#define SS 128
#define DD 512
#define HH 8
#define DH 64
#define FF 2048
#define RR 8
#define BS (BB*SS)          // 512
#define UU 262144           // 512*512
#define THRESH 0.1f

typedef __nv_bfloat16 bf16;

// ======================= helpers =======================
__device__ __forceinline__ uint32_t smem_u32(const void* p){
    uint32_t a;
    asm("{ .reg .u64 t; cvta.to.shared.u64 t, %1; cvt.u32.u64 %0, t; }" : "=r"(a) : "l"(p));
    return a;
}
__device__ __forceinline__ void ldsm4(uint32_t& r0, uint32_t& r1, uint32_t& r2, uint32_t& r3,
                                      uint32_t addr){
    asm volatile("ldmatrix.sync.aligned.m8n8.x4.shared.b16 {%0,%1,%2,%3}, [%4];"
                 : "=r"(r0), "=r"(r1), "=r"(r2), "=r"(r3) : "r"(addr));
}
__device__ __forceinline__ void mma16816(float* d, const uint32_t* a, const uint32_t* b){
    asm volatile("mma.sync.aligned.m16n8k16.row.col.f32.bf16.bf16.f32 "
                 "{%0,%1,%2,%3}, {%4,%5,%6,%7}, {%8,%9}, {%0,%1,%2,%3};"
                 : "+f"(d[0]), "+f"(d[1]), "+f"(d[2]), "+f"(d[3])
                 : "r"(a[0]), "r"(a[1]), "r"(a[2]), "r"(a[3]), "r"(b[0]), "r"(b[1]));
}
__device__ __forceinline__ void cpa16(uint32_t s, const void* g){
    asm volatile("cp.async.cg.shared.global [%0], [%1], 16;" :: "r"(s), "l"(g));
}
__device__ __forceinline__ void cpa_commit(){
    asm volatile("cp.async.commit_group;" ::: "memory");
}
template<int N> __device__ __forceinline__ void cpa_wait(){
    asm volatile("cp.async.wait_group %0;" :: "n"(N) : "memory");
}

// ======================= scratch (device globals) =======================
__device__ bf16  g_wTh[23*UU];          // packed transposed weights, hi
__device__ bf16  g_wTl[23*UU];          // packed transposed weights, lo
__device__ float g_b3[3*DD];            // packed q/k/v biases
__device__ bf16  g_xnh[UU], g_xnl[UU];
__device__ float g_qkv[3*UU];
__device__ float g_attn[BB*HH*SS*SS];
__device__ float g_am[BB*SS*SS];
__device__ bf16  g_ctxh[UU], g_ctxl[UU];
__device__ bf16  g_aoh[UU],  g_aol[UU];
__device__ bf16  g_hidh[BS*FF], g_hidl[BS*FF];
__device__ float g_nupart[4*UU];        // split-K partials for nu
__device__ float g_nu[UU];
__device__ bf16  g_nuh[UU], g_nul[UU];
__device__ float g_abt[10*UU];          // [0,1]=a/b parts, [2..9]=trans slabs [r][n][d]
__device__ int   g_rel[BB*SS*SS];
__device__ bf16  g_rsh[UU], g_rsl[UU];
__device__ float g_nr[UU];

struct WUnit { const float* src; int ld; long dst; int dld; };
__device__ WUnit g_wu[23];

// ======================= setup: weight-unit table + packed biases =======================
__global__ void setup_k(const float* wq, const float* wk, const float* wv, const float* wo,
                        const float* w1, const float* w2, const float* rc, const float* kg,
                        const float* s2n, const float* bq, const float* bk, const float* bvv)
{
    int t = threadIdx.x;
    if (t < DD) { g_b3[t] = bq[t]; g_b3[DD+t] = bk[t]; g_b3[2*DD+t] = bvv[t]; }
    if (t == 0) {
        const float* qkv[3] = {wq, wk, wv};
        for (int u = 0; u < 3; u++) g_wu[u] = {qkv[u], DD, (long)u*UU, DD};
        g_wu[3] = {wo, DD, 3L*UU, DD};
        for (int u = 0; u < 4; u++)                       // w1 [512][2048] -> [2048][512]
            g_wu[4+u] = {w1 + u*DD, FF, 4L*UU + (long)u*UU, DD};
        for (int u = 0; u < 4; u++)                       // w2 [2048][512] -> [512][2048]
            g_wu[8+u] = {w2 + (long)u*UU, DD, 8L*UU + (long)u*DD, FF};
        for (int u = 0; u < 2; u++)
            g_wu[12+u] = {rc + (long)u*UU, DD, (12L+u)*UU, DD};
        for (int u = 0; u < 8; u++)
            g_wu[14+u] = {kg + (long)u*UU, DD, (14L+u)*UU, DD};
        g_wu[22] = {s2n, DD, 22L*UU, DD};
    }
}

// ======================= weight transpose + fp32 -> bf16 hi/lo =======================
__global__ void wconv_k()
{
    __shared__ float tile[32][33];
    WUnit u = g_wu[blockIdx.z];
    int k0 = blockIdx.y * 32, n0 = blockIdx.x * 32;
    int tx = threadIdx.x, ty = threadIdx.y;        // (32, 8)
#pragma unroll
    for (int i = 0; i < 4; i++)
        tile[ty + 8*i][tx] = __ldg(u.src + (long)(k0 + ty + 8*i) * u.ld + n0 + tx);
    __syncthreads();
#pragma unroll
    for (int i = 0; i < 4; i++) {
        int n = n0 + ty + 8*i, k = k0 + tx;
        float v = tile[tx][ty + 8*i];
        bf16 h = __float2bfloat16(v);
        bf16 l = __float2bfloat16(v - __bfloat162float(h));
        long off = u.dst + (long)n * u.dld + k;
        g_wTh[off] = h; g_wTl[off] = l;
    }
}

// ======================= mma.sync bf16 3-pass GEMM, cp.async 2-stage, 3 CTA/SM ==========
#define FL_F32  1
#define FL_HILO 2
#define FL_RELU 4

#define TSTRIDE 144                      // smem row stride bytes (72 bf16)
#define TILE_B  9216                     // 64 rows * 144 B
#define STAGE_B 36864                    // 4 tiles
#define GSM     73728                    // 2 stages

__global__ void __launch_bounds__(256, 3)
gemm_mma(const bf16* __restrict__ Ah, const bf16* __restrict__ Al, int lda, long a_z,
         const bf16* __restrict__ Bh, const bf16* __restrict__ Bl, long b_z, int ldb,
         const float* __restrict__ bias, int bias_z,
         float* __restrict__ C, long c_z, int ldc,
         bf16* __restrict__ Ch, bf16* __restrict__ Cl, int ldch,
         int K, int flags)
{
    extern __shared__ char sm[];
    uint32_t sb = smem_u32(sm);
    const int tid = threadIdx.x, lane = tid & 31, wid = tid >> 5;
    const int wm = wid >> 2, wn = wid & 3;               // warp grid 2 x 4
    const int m0 = blockIdx.y * 64, n0 = blockIdx.x * 64, z = blockIdx.z;
    const bf16* Ahp = Ah + (long)z * a_z;
    const bf16* Alp = Al + (long)z * a_z;
    const bf16* Bhp = Bh + (long)z * b_z;
    const bf16* Blp = Bl + (long)z * b_z;

    const int ld_r = tid >> 3, ld_c = (tid & 7) * 8;
    const uint32_t s_wr = (uint32_t)(ld_r * TSTRIDE + ld_c * 2);

    const int a_r = (lane & 7) + ((lane >> 3) & 1) * 8;
    const int a_c8 = (lane >> 4) * 8;
    const uint32_t aoff = (uint32_t)((wm * 32 + a_r) * TSTRIDE + a_c8 * 2);
    const int b_r = (lane & 7) + (lane >> 4) * 8;
    const int b_c8 = ((lane >> 3) & 1) * 8;
    const uint32_t boff = (uint32_t)((wn * 16 + b_r) * TSTRIDE + b_c8 * 2);

    float acc[2][2][4];
#pragma unroll
    for (int i = 0; i < 2; i++)
#pragma unroll
        for (int j = 0; j < 2; j++)
#pragma unroll
            for (int q = 0; q < 4; q++) acc[i][j][q] = 0.f;

    uint32_t fah[2][2][4], fal[2][2][4], fbh[2][2][2], fbl[2][2][2];

    const int nch = K >> 6;

    auto issue = [&](int kk, int st){
        uint32_t base = sb + st * STAGE_B + s_wr;
        const bf16* ga0 = Ahp + (long)(m0 + ld_r) * lda + kk + ld_c;
        const bf16* ga1 = Alp + (long)(m0 + ld_r) * lda + kk + ld_c;
        const bf16* gb0 = Bhp + (long)(n0 + ld_r) * ldb + kk + ld_c;
        const bf16* gb1 = Blp + (long)(n0 + ld_r) * ldb + kk + ld_c;
        cpa16(base,                         ga0);
        cpa16(base + 32 * TSTRIDE,          ga0 + 32 * lda);
        cpa16(base + TILE_B,                ga1);
        cpa16(base + TILE_B + 32 * TSTRIDE, ga1 + 32 * lda);
        cpa16(base + 2 * TILE_B,                gb0);
        cpa16(base + 2 * TILE_B + 32 * TSTRIDE, gb0 + 32 * ldb);
        cpa16(base + 3 * TILE_B,                gb1);
        cpa16(base + 3 * TILE_B + 32 * TSTRIDE, gb1 + 32 * ldb);
        cpa_commit();
    };

    issue(0, 0);
    for (int i = 0; i < nch; i++) {
        if (i + 1 < nch) { issue((i + 1) << 6, (i + 1) & 1); cpa_wait<1>(); }
        else             { cpa_wait<0>(); }
        __syncthreads();

        uint32_t st = sb + (i & 1) * STAGE_B;

        // prologue fragments for ks=0
        {
            ldsm4(fbh[0][0][0], fbh[0][0][1], fbh[0][1][0], fbh[0][1][1], st + 2*TILE_B + boff);
            ldsm4(fbl[0][0][0], fbl[0][0][1], fbl[0][1][0], fbl[0][1][1], st + 3*TILE_B + boff);
#pragma unroll
            for (int mf = 0; mf < 2; mf++)
                ldsm4(fah[0][mf][0], fah[0][mf][1], fah[0][mf][2], fah[0][mf][3],
                      st + aoff + mf * (16*TSTRIDE));
#pragma unroll
            for (int mf = 0; mf < 2; mf++)
                ldsm4(fal[0][mf][0], fal[0][mf][1], fal[0][mf][2], fal[0][mf][3],
                      st + TILE_B + aoff + mf * (16*TSTRIDE));
        }

#pragma unroll
        for (int ks = 0; ks < 4; ks++) {
            const int cur = ks & 1, nxt = cur ^ 1;
            if (ks < 3) {
                uint32_t kb = (ks + 1) * 32;
                ldsm4(fbh[nxt][0][0], fbh[nxt][0][1], fbh[nxt][1][0], fbh[nxt][1][1],
                      st + 2*TILE_B + boff + kb);
                ldsm4(fbl[nxt][0][0], fbl[nxt][0][1], fbl[nxt][1][0], fbl[nxt][1][1],
                      st + 3*TILE_B + boff + kb);
#pragma unroll
                for (int mf = 0; mf < 2; mf++)
                    ldsm4(fah[nxt][mf][0], fah[nxt][mf][1], fah[nxt][mf][2], fah[nxt][mf][3],
                          st + aoff + mf * (16*TSTRIDE) + kb);
#pragma unroll
                for (int mf = 0; mf < 2; mf++)
                    ldsm4(fal[nxt][mf][0], fal[nxt][mf][1], fal[nxt][mf][2], fal[nxt][mf][3],
                          st + TILE_B + aoff + mf * (16*TSTRIDE) + kb);
            }
#pragma unroll
            for (int mf = 0; mf < 2; mf++)
#pragma unroll
                for (int nf = 0; nf < 2; nf++) mma16816(acc[mf][nf], fah[cur][mf], fbh[cur][nf]);
#pragma unroll
            for (int mf = 0; mf < 2; mf++)
#pragma unroll
                for (int nf = 0; nf < 2; nf++) mma16816(acc[mf][nf], fah[cur][mf], fbl[cur][nf]);
#pragma unroll
            for (int mf = 0; mf < 2; mf++)
#pragma unroll
                for (int nf = 0; nf < 2; nf++) mma16816(acc[mf][nf], fal[cur][mf], fbh[cur][nf]);
        }
        __syncthreads();
    }

    // epilogue
    const int g = lane >> 2, tg = lane & 3;
    const float* bp = bias ? bias + (long)z * bias_z : nullptr;
    float* Cz = C ? C + (long)z * c_z : nullptr;
#pragma unroll
    for (int mf = 0; mf < 2; mf++) {
#pragma unroll
        for (int nf = 0; nf < 2; nf++) {
            int row = m0 + wm * 32 + mf * 16 + g;
            int col = n0 + wn * 16 + nf * 8 + tg * 2;
            float v0 = acc[mf][nf][0], v1 = acc[mf][nf][1];
            float v2 = acc[mf][nf][2], v3 = acc[mf][nf][3];
            if (bp) {
                float bb0 = __ldg(bp + col), bb1 = __ldg(bp + col + 1);
                v0 += bb0; v1 += bb1; v2 += bb0; v3 += bb1;
            }
            if (flags & FL_RELU) {
                v0 = fmaxf(v0, 0.f); v1 = fmaxf(v1, 0.f);
                v2 = fmaxf(v2, 0.f); v3 = fmaxf(v3, 0.f);
            }
            if (flags & FL_F32) {
                *(float2*)&Cz[(long)row * ldc + col] = make_float2(v0, v1);
                *(float2*)&Cz[(long)(row + 8) * ldc + col] = make_float2(v2, v3);
            }
            if (flags & FL_HILO) {
                bf16 h0 = __float2bfloat16(v0), h1 = __float2bfloat16(v1);
                bf16 h2 = __float2bfloat16(v2), h3 = __float2bfloat16(v3);
                __nv_bfloat162 ph0; ph0.x = h0; ph0.y = h1;
                __nv_bfloat162 ph1; ph1.x = h2; ph1.y = h3;
                __nv_bfloat162 pl0, pl1;
                pl0.x = __float2bfloat16(v0 - __bfloat162float(h0));
                pl0.y = __float2bfloat16(v1 - __bfloat162float(h1));
                pl1.x = __float2bfloat16(v2 - __bfloat162float(h2));
                pl1.y = __float2bfloat16(v3 - __bfloat162float(h3));
                *(__nv_bfloat162*)&Ch[(long)row * ldch + col] = ph0;
                *(__nv_bfloat162*)&Cl[(long)row * ldch + col] = pl0;
                *(__nv_bfloat162*)&Ch[(long)(row + 8) * ldch + col] = ph1;
                *(__nv_bfloat162*)&Cl[(long)(row + 8) * ldch + col] = pl1;
            }
        }
    }
}

// ======================= LayerNorms =======================
__global__ void ln1_k(const float* __restrict__ in, const float* __restrict__ g,
                      const float* __restrict__ b, bf16* __restrict__ oh, bf16* __restrict__ ol)
{
    int row = blockIdx.x, t = threadIdx.x;   // 256 threads
    __shared__ float rbuf[256];
    long base = (long)row * DD;
    float v0 = in[base + t], v1 = in[base + t + 256];
    rbuf[t] = v0 + v1; __syncthreads();
    for (int s = 128; s > 0; s >>= 1) { if (t < s) rbuf[t] += rbuf[t + s]; __syncthreads(); }
    float mean = rbuf[0] * (1.0f / 512.0f);
    __syncthreads();
    float d0 = v0 - mean, d1 = v1 - mean;
    rbuf[t] = d0 * d0 + d1 * d1; __syncthreads();
    for (int s = 128; s > 0; s >>= 1) { if (t < s) rbuf[t] += rbuf[t + s]; __syncthreads(); }
    float rs = rsqrtf(rbuf[0] * (1.0f / 512.0f) + 1e-5f);
    float o0 = d0 * rs * g[t] + b[t];
    float o1 = d1 * rs * g[t + 256] + b[t + 256];
    bf16 h0 = __float2bfloat16(o0), h1 = __float2bfloat16(o1);
    oh[base + t] = h0;       ol[base + t]       = __float2bfloat16(o0 - __bfloat162float(h0));
    oh[base + t + 256] = h1; ol[base + t + 256] = __float2bfloat16(o1 - __bfloat162float(h1));
}

__global__ void ln2_k(const float* __restrict__ in, const float* __restrict__ add,
                      const float* __restrict__ g, const float* __restrict__ b,
                      float* __restrict__ out)
{
    int row = blockIdx.x, t = threadIdx.x;
    __shared__ float rbuf[256];
    long base = (long)row * DD;
    float v0 = in[base + t] + add[base + t];
    float v1 = in[base + t + 256] + add[base + t + 256];
    rbuf[t] = v0 + v1; __syncthreads();
    for (int s = 128; s > 0; s >>= 1) { if (t < s) rbuf[t] += rbuf[t + s]; __syncthreads(); }
    float mean = rbuf[0] * (1.0f / 512.0f);
    __syncthreads();
    float d0 = v0 - mean, d1 = v1 - mean;
    rbuf[t] = d0 * d0 + d1 * d1; __syncthreads();
    for (int s = 128; s > 0; s >>= 1) { if (t < s) rbuf[t] += rbuf[t + s]; __syncthreads(); }
    float rs = rsqrtf(rbuf[0] * (1.0f / 512.0f) + 1e-5f);
    out[base + t]       = d0 * rs * g[t]       + b[t];
    out[base + t + 256] = d1 * rs * g[t + 256] + b[t + 256];
}

// ======================= attention: scores+softmax, 16-row tiles =======================
__global__ void attn_scores_k(const float* __restrict__ q, const float* __restrict__ k,
                              float* __restrict__ attn)
{
    int it = blockIdx.x, h = blockIdx.y, b = blockIdx.z;  // 256 thr
    int t = threadIdx.x;
    int i0 = it * 16;
    __shared__ float ks[SS][DH + 1];
    __shared__ float qs[16][DH + 1];
    __shared__ float P[16][SS];
    const float* kbase = k + (long)b * SS * DD + h * DH;
    const float* qbase = q + (long)b * SS * DD + h * DH;
    for (int idx = t; idx < SS * DH; idx += 256) {
        int j = idx >> 6, d = idx & 63;
        ks[j][d] = kbase[(long)j * DD + d];
    }
    for (int idx = t; idx < 16 * DH; idx += 256) {
        int r = idx >> 6, d = idx & 63;
        qs[r][d] = qbase[(long)(i0 + r) * DD + d];
    }
    __syncthreads();
    {
        int j = t & 127, grp = t >> 7;
#pragma unroll
        for (int r = 0; r < 8; r++) {
            int i = grp * 8 + r;
            float acc = 0.f;
#pragma unroll
            for (int d = 0; d < DH; d++) acc += qs[i][d] * ks[j][d];
            P[i][j] = acc * 0.125f;
        }
    }
    __syncthreads();
    {
        int w = t >> 5, ln = t & 31;
        long obase = (((long)(b * HH + h) * SS) + i0) * SS;
#pragma unroll
        for (int rr = 0; rr < 2; rr++) {
            int i = w * 2 + rr;
            float m = -1e30f;
#pragma unroll
            for (int c = 0; c < 4; c++) m = fmaxf(m, P[i][ln + c * 32]);
#pragma unroll
            for (int o = 16; o > 0; o >>= 1) m = fmaxf(m, __shfl_xor_sync(0xffffffffu, m, o));
            float s = 0.f, e[4];
#pragma unroll
            for (int c = 0; c < 4; c++) { e[c] = expf(P[i][ln + c * 32] - m); s += e[c]; }
#pragma unroll
            for (int o = 16; o > 0; o >>= 1) s += __shfl_xor_sync(0xffffffffu, s, o);
            float inv = 1.0f / s;
#pragma unroll
            for (int c = 0; c < 4; c++) attn[obase + (long)i * SS + ln + c * 32] = e[c] * inv;
        }
    }
}

__global__ void am_k(const float* __restrict__ attn, float* __restrict__ am)
{
    int bi = blockIdx.x;
    int b = bi >> 7, i = bi & 127, t = threadIdx.x;  // 128 thr
    float s = 0.f;
#pragma unroll
    for (int h = 0; h < HH; h++)
        s += attn[(((long)(b * HH + h) * SS) + i) * SS + t];
    am[(long)bi * SS + t] = s * 0.125f;
}

// ======================= attention: ctx = P @ V, 16-row tiles =======================
__global__ void attn_ctx_k(const float* __restrict__ attn, const float* __restrict__ v,
                           bf16* __restrict__ ch, bf16* __restrict__ cl)
{
    int it = blockIdx.x, h = blockIdx.y, b = blockIdx.z;  // 256 thr
    int t = threadIdx.x;
    int i0 = it * 16;
    int d = t & 63, ig = t >> 6;          // ig in 0..3; rows i = ig + 4*r
    __shared__ float vs[SS][DH + 1];
    __shared__ float at[16][SS];
    const float* vbase = v + (long)b * SS * DD + h * DH;
    for (int idx = t; idx < SS * DH; idx += 256) {
        int j = idx >> 6, dd = idx & 63;
        vs[j][dd] = vbase[(long)j * DD + dd];
    }
    long arow = (((long)(b * HH + h) * SS) + i0) * SS;
    for (int idx = t; idx < 16 * SS; idx += 256)
        at[idx >> 7][idx & 127] = attn[arow + (long)(idx >> 7) * SS + (idx & 127)];
    __syncthreads();

    float acc[4] = {0.f, 0.f, 0.f, 0.f};
#pragma unroll
    for (int jh = 0; jh < 2; jh++) {
        float vreg[64];
#pragma unroll
        for (int jj = 0; jj < 64; jj++) vreg[jj] = vs[jh * 64 + jj][d];
#pragma unroll
        for (int r = 0; r < 4; r++) {
            int i = ig + 4 * r;
            float a = acc[r];
#pragma unroll
            for (int jj = 0; jj < 64; jj++) a += at[i][jh * 64 + jj] * vreg[jj];
            acc[r] = a;
        }
    }
#pragma unroll
    for (int r = 0; r < 4; r++) {
        int i = ig + 4 * r;
        long o = (long)(b * SS + i0 + i) * DD + h * DH + d;
        bf16 hh = __float2bfloat16(acc[r]);
        ch[o] = hh; cl[o] = __float2bfloat16(acc[r] - __bfloat162float(hh));
    }
}

// ======================= nu: reduce split-K partials + bias + hi/lo =======================
__global__ void conv_nu_k(const float* __restrict__ P, const float* __restrict__ b2,
                          float* __restrict__ nu, bf16* __restrict__ H, bf16* __restrict__ L)
{
    int row = blockIdx.x, t = threadIdx.x;  // 256
    for (int c = t; c < DD; c += 256) {
        long i = (long)row * DD + c;
        float v = b2[c] + P[i] + P[UU + i] + P[2L*UU + i] + P[3L*UU + i];
        nu[i] = v;
        bf16 h = __float2bfloat16(v);
        H[i] = h; L[i] = __float2bfloat16(v - __bfloat162float(h));
    }
}

// ======================= pair relation classifier =======================
__global__ void pair_k(const float* __restrict__ ap, const float* __restrict__ bp,
                       const float* __restrict__ rc_b1, const float* __restrict__ rc_w2,
                       const float* __restrict__ rc_b2, const float* __restrict__ am,
                       int* __restrict__ rel)
{
    int b = blockIdx.z;
    int u0 = blockIdx.y * 16, v0 = blockIdx.x * 16;
    int t = threadIdx.x;                 // 256
    int ul = t >> 4, vl = t & 15;
    __shared__ float sA[16][65], sB[16][65], sW[64][8], sC[64];
    float acc[RR];
#pragma unroll
    for (int r = 0; r < RR; r++) acc[r] = rc_b2[r];

    for (int c0 = 0; c0 < DD; c0 += 64) {
        for (int idx = t; idx < 1024; idx += 256) {
            int rr = idx >> 6, cc = idx & 63;
            sA[rr][cc] = ap[(long)(b * SS + u0 + rr) * DD + c0 + cc];
            sB[rr][cc] = bp[(long)(b * SS + v0 + rr) * DD + c0 + cc];
        }
        for (int idx = t; idx < 512; idx += 256)
            sW[idx >> 3][idx & 7] = rc_w2[(long)(c0 + (idx >> 3)) * RR + (idx & 7)];
        if (t < 64) sC[t] = rc_b1[c0 + t];
        __syncthreads();
#pragma unroll 4
        for (int dd = 0; dd < 64; dd++) {
            float hsum = sA[ul][dd] + sB[vl][dd] + sC[dd];
            hsum = fmaxf(hsum, 0.f);
            float4 w0 = *(float4*)&sW[dd][0];
            float4 w1 = *(float4*)&sW[dd][4];
            acc[0] += hsum * w0.x; acc[1] += hsum * w0.y;
            acc[2] += hsum * w0.z; acc[3] += hsum * w0.w;
            acc[4] += hsum * w1.x; acc[5] += hsum * w1.y;
            acc[6] += hsum * w1.z; acc[7] += hsum * w1.w;
        }
        __syncthreads();
    }
    int pred = 0; float best = acc[0];
#pragma unroll
    for (int r = 1; r < RR; r++) if (acc[r] > best) { best = acc[r]; pred = r; }
    int u = u0 + ul, v = v0 + vl;
    float amv = am[((long)b * SS + u) * SS + v];
    int valid = (amv > THRESH) && (u != v) && (pred != 0);
    rel[((long)b * SS + u) * SS + v] = valid ? pred : 0;
}

// ======================= edge aggregation (trans slabs [r][n][d]) =======================
__global__ void agg_k(const int* __restrict__ rel, const float* __restrict__ trans,
                      const float* __restrict__ nu, bf16* __restrict__ rh, bf16* __restrict__ rl)
{
    int bv = blockIdx.x;                 // b*S + v
    int b = bv >> 7, v = bv & 127, t = threadIdx.x;   // 256
    __shared__ int sr[SS];
    if (t < SS) sr[t] = rel[((long)b * SS + t) * SS + v];
    __syncthreads();
    float a0 = 0.f, a1 = 0.f;
    for (int u = 0; u < SS; u++) {
        int r = sr[u];
        if (r) {
            const float* tr = trans + (long)r * UU + (long)(b * SS + u) * DD;
            a0 += tr[t]; a1 += tr[t + 256];
        }
    }
    long row = (long)bv * DD;
    float v0 = nu[row + t] + a0;
    float v1 = nu[row + t + 256] + a1;
    bf16 h0 = __float2bfloat16(v0), h1 = __float2bfloat16(v1);
    rh[row + t] = h0;       rl[row + t]       = __float2bfloat16(v0 - __bfloat162float(h0));
    rh[row + t + 256] = h1; rl[row + t + 256] = __float2bfloat16(v1 - __bfloat162float(h1));
}

// ======================= launch =======================
extern "C" void kernel_launch(void* const* d_in, const int* in_sizes, int n_in,
                              void* d_out, int out_size)
{
    const float* x     = (const float*)d_in[0];
    const float* ln1_g = (const float*)d_in[1];
    const float* ln1_b = (const float*)d_in[2];
    const float* wq    = (const float*)d_in[3];
    const float* bq    = (const float*)d_in[4];
    const float* wk    = (const float*)d_in[5];
    const float* bk    = (const float*)d_in[6];
    const float* wv    = (const float*)d_in[7];
    const float* bvv   = (const float*)d_in[8];
    const float* wo    = (const float*)d_in[9];
    const float* bo    = (const float*)d_in[10];
    const float* w1    = (const float*)d_in[11];
    const float* b1    = (const float*)d_in[12];
    const float* w2    = (const float*)d_in[13];
    const float* b2    = (const float*)d_in[14];
    const float* rc_w1 = (const float*)d_in[15];
    const float* rc_b1 = (const float*)d_in[16];
    const float* rc_w2 = (const float*)d_in[17];
    const float* rc_b2 = (const float*)d_in[18];
    const float* kg_w  = (const float*)d_in[19];
    const float* s2n_w = (const float*)d_in[20];
    const float* s2n_b = (const float*)d_in[21];
    const float* ln2_g = (const float*)d_in[22];
    const float* ln2_b = (const float*)d_in[23];
    float* out = (float*)d_out;

    bf16 *wTh, *wTl, *xnh, *xnl, *ctxh, *ctxl, *aoh, *aol, *hidh, *hidl, *nuh, *nul, *rsh, *rsl;
    float *b3, *qkv, *attn, *am, *nupart, *nu, *abt, *nr;
    int *rel;
    cudaGetSymbolAddress((void**)&wTh, g_wTh);   cudaGetSymbolAddress((void**)&wTl, g_wTl);
    cudaGetSymbolAddress((void**)&b3, g_b3);
    cudaGetSymbolAddress((void**)&xnh, g_xnh);   cudaGetSymbolAddress((void**)&xnl, g_xnl);
    cudaGetSymbolAddress((void**)&qkv, g_qkv);
    cudaGetSymbolAddress((void**)&attn, g_attn); cudaGetSymbolAddress((void**)&am, g_am);
    cudaGetSymbolAddress((void**)&ctxh, g_ctxh); cudaGetSymbolAddress((void**)&ctxl, g_ctxl);
    cudaGetSymbolAddress((void**)&aoh, g_aoh);   cudaGetSymbolAddress((void**)&aol, g_aol);
    cudaGetSymbolAddress((void**)&hidh, g_hidh); cudaGetSymbolAddress((void**)&hidl, g_hidl);
    cudaGetSymbolAddress((void**)&nupart, g_nupart);
    cudaGetSymbolAddress((void**)&nu, g_nu);
    cudaGetSymbolAddress((void**)&nuh, g_nuh);   cudaGetSymbolAddress((void**)&nul, g_nul);
    cudaGetSymbolAddress((void**)&abt, g_abt);
    cudaGetSymbolAddress((void**)&rel, g_rel);
    cudaGetSymbolAddress((void**)&rsh, g_rsh);   cudaGetSymbolAddress((void**)&rsl, g_rsl);
    cudaGetSymbolAddress((void**)&nr, g_nr);

    cudaFuncSetAttribute(gemm_mma, cudaFuncAttributeMaxDynamicSharedMemorySize, GSM);
    cudaFuncSetAttribute(gemm_mma, cudaFuncAttributePreferredSharedMemoryCarveout, 100);

    // weight prep
    setup_k<<<1, 512>>>(wq, wk, wv, wo, w1, w2, rc_w1, kg_w, s2n_w, bq, bk, bvv);
    wconv_k<<<dim3(16, 16, 23), dim3(32, 8)>>>();

    // ln1 -> xn (hi/lo)
    ln1_k<<<BS, 256>>>(x, ln1_g, ln1_b, xnh, xnl);

    // QKV (z=3), fp32 out
    gemm_mma<<<dim3(8, 8, 3), 256, GSM>>>(xnh, xnl, DD, 0, wTh, wTl, UU, DD,
                                          b3, DD, qkv, UU, DD, nullptr, nullptr, 0,
                                          DD, FL_F32);
    // attention (16-row tiled)
    attn_scores_k<<<dim3(8, HH, BB), 256>>>(qkv, qkv + UU, attn);
    am_k<<<BS, 128>>>(attn, am);
    attn_ctx_k<<<dim3(8, HH, BB), 256>>>(attn, qkv + 2 * UU, ctxh, ctxl);

    // ao = ctx @ wo + bo  (hi/lo only)
    gemm_mma<<<dim3(8, 8, 1), 256, GSM>>>(ctxh, ctxl, DD, 0, wTh + 3L*UU, wTl + 3L*UU, 0, DD,
                                          bo, 0, nullptr, 0, 0, aoh, aol, DD,
                                          DD, FL_HILO);
    // hid = relu(ao @ w1 + b1) (hi/lo only, N=2048)
    gemm_mma<<<dim3(32, 8, 1), 256, GSM>>>(aoh, aol, DD, 0, wTh + 4L*UU, wTl + 4L*UU, 0, DD,
                                           b1, 0, nullptr, 0, 0, hidh, hidl, FF,
                                           DD, FL_HILO | FL_RELU);
    // nu partials = hid @ w2  (split-K z=4 into 4 slabs)
    gemm_mma<<<dim3(8, 8, 4), 256, GSM>>>(hidh, hidl, FF, DD, wTh + 8L*UU, wTl + 8L*UU, DD, FF,
                                          nullptr, 0, nupart, UU, DD, nullptr, nullptr, 0,
                                          DD, FL_F32);
    conv_nu_k<<<BS, 256>>>(nupart, b2, nu, nuh, nul);

    // fused: a/b parts (z=0,1) + RGCN transforms (z=2..9) in one launch
    gemm_mma<<<dim3(8, 8, 10), 256, GSM>>>(nuh, nul, DD, 0, wTh + 12L*UU, wTl + 12L*UU, UU, DD,
                                           nullptr, 0, abt, UU, DD, nullptr, nullptr, 0,
                                           DD, FL_F32);
    // edges + aggregation (trans slabs start at abt + 2*UU)
    pair_k<<<dim3(8, 8, BB), 256>>>(abt, abt + UU, rc_b1, rc_w2, rc_b2, am, rel);
    agg_k<<<BS, 256>>>(rel, abt + 2L*UU, nu, rsh, rsl);

    // s2n projection, fp32
    gemm_mma<<<dim3(8, 8, 1), 256, GSM>>>(rsh, rsl, DD, 0, wTh + 22L*UU, wTl + 22L*UU, 0, DD,
                                          s2n_b, 0, nr, 0, DD, nullptr, nullptr, 0,
                                          DD, FL_F32);
    // final residual LN
    ln2_k<<<BS, 256>>>(nr, x, ln2_g, ln2_b, out);
}